// round 3
// baseline (speedup 1.0000x reference)
#include <cuda_runtime.h>
#include <math.h>

// Problem constants
#define BB   4
#define LL   1024
#define DD   1024
#define HH   16
#define HDIM 64
#define FFD  4096
#define MM   (BB * LL)   // 4096 rows

// ---------------------------------------------------------------------------
// Scratch (static __device__ arrays; no allocation allowed)
// ---------------------------------------------------------------------------
__device__ float g_q   [MM * DD];
__device__ float g_k   [MM * DD];
__device__ float g_v   [MM * DD];
__device__ float g_ctx [MM * DD];
__device__ float g_proj[MM * DD];
__device__ float g_t1  [MM * DD];
__device__ float g_a1  [MM * DD];
__device__ float g_t2  [MM * DD];
__device__ float g_a2  [MM * DD];
__device__ float g_ffh [MM * FFD];

// ---------------------------------------------------------------------------
// SGEMM: C[M,N] = A[M,K] @ B[K,N] (+bias) (+relu). Row-major. M,N mult of 128,
// K mult of 8. 256 threads, 128x128 tile, 8x8 per thread.
// ---------------------------------------------------------------------------
template <bool RELU, bool BIAS>
__global__ void __launch_bounds__(256) sgemm_kernel(
    const float* __restrict__ A, const float* __restrict__ Bm,
    const float* __restrict__ bias, float* __restrict__ C,
    int M, int N, int K)
{
    __shared__ float As[8][128];
    __shared__ float Bs[8][128];

    const int tid = threadIdx.x;
    const int bm = blockIdx.y * 128;
    const int bn = blockIdx.x * 128;

    const int a_row = tid >> 1;          // 0..127
    const int a_col = (tid & 1) << 2;    // 0 or 4
    const int b_row = tid >> 5;          // 0..7
    const int b_col = (tid & 31) << 2;   // 0..124
    const int tr = tid >> 4;             // 0..15
    const int tc = tid & 15;             // 0..15

    const float* Ap = A + (size_t)(bm + a_row) * K + a_col;
    const float* Bp = Bm + (size_t)b_row * N + bn + b_col;

    float acc[8][8];
#pragma unroll
    for (int i = 0; i < 8; i++)
#pragma unroll
        for (int j = 0; j < 8; j++) acc[i][j] = 0.f;

    for (int k0 = 0; k0 < K; k0 += 8) {
        float4 av = *(const float4*)(Ap + k0);
        float4 bv = *(const float4*)(Bp + (size_t)k0 * N);
        __syncthreads();
        As[a_col + 0][a_row] = av.x;
        As[a_col + 1][a_row] = av.y;
        As[a_col + 2][a_row] = av.z;
        As[a_col + 3][a_row] = av.w;
        *(float4*)&Bs[b_row][b_col] = bv;
        __syncthreads();
#pragma unroll
        for (int k = 0; k < 8; k++) {
            float4 a0 = *(float4*)&As[k][tr << 2];
            float4 a1 = *(float4*)&As[k][64 + (tr << 2)];
            float4 b0 = *(float4*)&Bs[k][tc << 2];
            float4 b1 = *(float4*)&Bs[k][64 + (tc << 2)];
            float af[8] = {a0.x, a0.y, a0.z, a0.w, a1.x, a1.y, a1.z, a1.w};
            float bf[8] = {b0.x, b0.y, b0.z, b0.w, b1.x, b1.y, b1.z, b1.w};
#pragma unroll
            for (int i = 0; i < 8; i++)
#pragma unroll
                for (int j = 0; j < 8; j++)
                    acc[i][j] = fmaf(af[i], bf[j], acc[i][j]);
        }
    }

#pragma unroll
    for (int ii = 0; ii < 2; ii++) {
#pragma unroll
        for (int i2 = 0; i2 < 4; i2++) {
            int row = bm + ii * 64 + (tr << 2) + i2;
#pragma unroll
            for (int jj = 0; jj < 2; jj++) {
                int col = bn + jj * 64 + (tc << 2);
                float4 o;
                o.x = acc[ii * 4 + i2][jj * 4 + 0];
                o.y = acc[ii * 4 + i2][jj * 4 + 1];
                o.z = acc[ii * 4 + i2][jj * 4 + 2];
                o.w = acc[ii * 4 + i2][jj * 4 + 3];
                if (BIAS) {
                    o.x += bias[col + 0];
                    o.y += bias[col + 1];
                    o.z += bias[col + 2];
                    o.w += bias[col + 3];
                }
                if (RELU) {
                    o.x = fmaxf(o.x, 0.f);
                    o.y = fmaxf(o.y, 0.f);
                    o.z = fmaxf(o.z, 0.f);
                    o.w = fmaxf(o.w, 0.f);
                }
                *(float4*)&C[(size_t)row * N + col] = o;
            }
        }
    }
}

// ---------------------------------------------------------------------------
// Fused attention (flash-style, fp32).
// Grid: (L/64, B*H). 256 threads. Dynamic smem: Q,K,V,P tiles (64x64, pad 68)
// + 64-float pad-mask slice.
// ctx layout: [B, L, D] with head h occupying columns [h*64, h*64+64).
// ---------------------------------------------------------------------------
#define SATT 68
#define ATT_SMEM_FLOATS (4 * 64 * SATT + 64)

__global__ void __launch_bounds__(256) attn_kernel(
    const float* __restrict__ Qb, const float* __restrict__ Kb,
    const float* __restrict__ Vb, const float* __restrict__ mask,
    const int* __restrict__ pad, float* __restrict__ ctx)
{
    extern __shared__ float sm[];
    float* Qs   = sm;
    float* Ks   = Qs + 64 * SATT;
    float* Vs   = Ks + 64 * SATT;
    float* Ps   = Vs + 64 * SATT;
    float* pads = Ps + 64 * SATT;

    const int b  = blockIdx.y >> 4;   // / HH
    const int h  = blockIdx.y & 15;   // % HH
    const int q0 = blockIdx.x * 64;
    const int tid = threadIdx.x;
    const int tr = tid >> 4;          // 0..15
    const int tc = tid & 15;          // 0..15

    // Load Q tile [64 rows x 64 dims]
    for (int i = tid; i < 64 * 16; i += 256) {
        int r = i >> 4, c = (i & 15) << 2;
        *(float4*)&Qs[r * SATT + c] =
            *(const float4*)&Qb[(size_t)(b * LL + q0 + r) * DD + h * HDIM + c];
    }

    float acc[4][4];
    float mrow[4], lrow[4];
#pragma unroll
    for (int i = 0; i < 4; i++) {
        mrow[i] = -1e30f;
        lrow[i] = 0.f;
#pragma unroll
        for (int j = 0; j < 4; j++) acc[i][j] = 0.f;
    }

    for (int kt = 0; kt < LL / 64; kt++) {
        const int k0 = kt * 64;
        __syncthreads();   // protect prev-iter reads of Ks/Vs/Ps (and Q on kt=0)
        for (int i = tid; i < 64 * 16; i += 256) {
            int r = i >> 4, c = (i & 15) << 2;
            size_t go = (size_t)(b * LL + k0 + r) * DD + h * HDIM + c;
            *(float4*)&Ks[r * SATT + c] = *(const float4*)&Kb[go];
            *(float4*)&Vs[r * SATT + c] = *(const float4*)&Vb[go];
        }
        if (tid < 64) pads[tid] = (float)pad[b * LL + k0 + tid];
        __syncthreads();

        // S = Q K^T : thread owns rows (tr+16i), cols (tc+16j)
        float s[4][4];
#pragma unroll
        for (int i = 0; i < 4; i++)
#pragma unroll
            for (int j = 0; j < 4; j++) s[i][j] = 0.f;

#pragma unroll
        for (int d = 0; d < HDIM; d += 4) {
            float4 q4[4], k4[4];
#pragma unroll
            for (int i = 0; i < 4; i++) q4[i] = *(float4*)&Qs[(tr + 16 * i) * SATT + d];
#pragma unroll
            for (int j = 0; j < 4; j++) k4[j] = *(float4*)&Ks[(tc + 16 * j) * SATT + d];
#pragma unroll
            for (int i = 0; i < 4; i++)
#pragma unroll
                for (int j = 0; j < 4; j++)
                    s[i][j] += q4[i].x * k4[j].x + q4[i].y * k4[j].y +
                               q4[i].z * k4[j].z + q4[i].w * k4[j].w;
        }

        // scale + masks + online softmax (rows shared by the 16 tc-lanes)
#pragma unroll
        for (int i = 0; i < 4; i++) {
            const int qr = q0 + tr + 16 * i;
            float sv[4];
#pragma unroll
            for (int j = 0; j < 4; j++) {
                const int kc = k0 + tc + 16 * j;
                sv[j] = s[i][j] * 0.125f + mask[(size_t)qr * LL + kc] + pads[tc + 16 * j];
            }
            float rm = fmaxf(fmaxf(sv[0], sv[1]), fmaxf(sv[2], sv[3]));
#pragma unroll
            for (int o = 8; o >= 1; o >>= 1)
                rm = fmaxf(rm, __shfl_xor_sync(0xffffffffu, rm, o));
            const float mnew = fmaxf(mrow[i], rm);
            const float corr = __expf(mrow[i] - mnew);
            float rs = 0.f;
#pragma unroll
            for (int j = 0; j < 4; j++) {
                float p = __expf(sv[j] - mnew);
                Ps[(tr + 16 * i) * SATT + tc + 16 * j] = p;
                rs += p;
            }
#pragma unroll
            for (int o = 8; o >= 1; o >>= 1)
                rs += __shfl_xor_sync(0xffffffffu, rs, o);
            lrow[i] = lrow[i] * corr + rs;
            mrow[i] = mnew;
#pragma unroll
            for (int j = 0; j < 4; j++) acc[i][j] *= corr;
        }
        __syncthreads();   // Ps complete

        // O += P @ V : acc cols are head-dims (tc*4 + j), contiguous float4
#pragma unroll
        for (int k = 0; k < 64; k += 4) {
            float p4[4][4];
#pragma unroll
            for (int i = 0; i < 4; i++)
                *(float4*)p4[i] = *(float4*)&Ps[(tr + 16 * i) * SATT + k];
#pragma unroll
            for (int kk = 0; kk < 4; kk++) {
                float4 v4 = *(float4*)&Vs[(k + kk) * SATT + (tc << 2)];
#pragma unroll
                for (int i = 0; i < 4; i++) {
                    acc[i][0] = fmaf(p4[i][kk], v4.x, acc[i][0]);
                    acc[i][1] = fmaf(p4[i][kk], v4.y, acc[i][1]);
                    acc[i][2] = fmaf(p4[i][kk], v4.z, acc[i][2]);
                    acc[i][3] = fmaf(p4[i][kk], v4.w, acc[i][3]);
                }
            }
        }
    }

#pragma unroll
    for (int i = 0; i < 4; i++) {
        const float inv = 1.f / lrow[i];
        float4 o;
        o.x = acc[i][0] * inv;
        o.y = acc[i][1] * inv;
        o.z = acc[i][2] * inv;
        o.w = acc[i][3] * inv;
        *(float4*)&ctx[(size_t)(b * LL + q0 + tr + 16 * i) * DD + h * HDIM + (tc << 2)] = o;
    }
}

// ---------------------------------------------------------------------------
// out = LayerNorm(x + r) * g + b   (one row per block, D=1024, 256 threads)
// ---------------------------------------------------------------------------
__global__ void __launch_bounds__(256) ln_residual_kernel(
    const float* __restrict__ x, const float* __restrict__ r,
    const float* __restrict__ g, const float* __restrict__ be,
    float* __restrict__ out)
{
    __shared__ float red[8];
    const int row = blockIdx.x;
    const int t = threadIdx.x;

    const float4 a = ((const float4*)(x + (size_t)row * DD))[t];
    const float4 c = ((const float4*)(r + (size_t)row * DD))[t];
    float4 v = make_float4(a.x + c.x, a.y + c.y, a.z + c.z, a.w + c.w);

    float s = v.x + v.y + v.z + v.w;
#pragma unroll
    for (int o = 16; o >= 1; o >>= 1) s += __shfl_xor_sync(0xffffffffu, s, o);
    if ((t & 31) == 0) red[t >> 5] = s;
    __syncthreads();
    float tot = red[0] + red[1] + red[2] + red[3] + red[4] + red[5] + red[6] + red[7];
    const float mean = tot * (1.0f / DD);

    const float dx0 = v.x - mean, dx1 = v.y - mean, dx2 = v.z - mean, dx3 = v.w - mean;
    float sq = dx0 * dx0 + dx1 * dx1 + dx2 * dx2 + dx3 * dx3;
#pragma unroll
    for (int o = 16; o >= 1; o >>= 1) sq += __shfl_xor_sync(0xffffffffu, sq, o);
    __syncthreads();
    if ((t & 31) == 0) red[t >> 5] = sq;
    __syncthreads();
    float var = (red[0] + red[1] + red[2] + red[3] + red[4] + red[5] + red[6] + red[7]) * (1.0f / DD);
    const float rstd = rsqrtf(var + 1e-5f);

    const float4 gg = ((const float4*)g)[t];
    const float4 bb = ((const float4*)be)[t];
    float4 o;
    o.x = dx0 * rstd * gg.x + bb.x;
    o.y = dx1 * rstd * gg.y + bb.y;
    o.z = dx2 * rstd * gg.z + bb.z;
    o.w = dx3 * rstd * gg.w + bb.w;
    ((float4*)(out + (size_t)row * DD))[t] = o;
}

// ---------------------------------------------------------------------------
// Launch
// ---------------------------------------------------------------------------
extern "C" void kernel_launch(void* const* d_in, const int* in_sizes, int n_in,
                              void* d_out, int out_size)
{
    const float* T    = (const float*)d_in[0];
    const float* A    = (const float*)d_in[1];
    const float* mask = (const float*)d_in[2];
    const int*   pad  = (const int*)  d_in[3];
    const float* Wq   = (const float*)d_in[4];
    const float* bq   = (const float*)d_in[5];
    const float* Wk   = (const float*)d_in[6];
    const float* bk   = (const float*)d_in[7];
    const float* Wv   = (const float*)d_in[8];
    const float* bv   = (const float*)d_in[9];
    const float* Wo   = (const float*)d_in[10];
    const float* fW1  = (const float*)d_in[11];
    const float* fb1  = (const float*)d_in[12];
    const float* fW2  = (const float*)d_in[13];
    const float* fb2  = (const float*)d_in[14];
    const float* lng  = (const float*)d_in[15];
    const float* lnb  = (const float*)d_in[16];
    float* out = (float*)d_out;

    float *q, *k, *v, *ctx, *proj, *t1, *a1, *t2, *a2, *ffh;
    cudaGetSymbolAddress((void**)&q,    g_q);
    cudaGetSymbolAddress((void**)&k,    g_k);
    cudaGetSymbolAddress((void**)&v,    g_v);
    cudaGetSymbolAddress((void**)&ctx,  g_ctx);
    cudaGetSymbolAddress((void**)&proj, g_proj);
    cudaGetSymbolAddress((void**)&t1,   g_t1);
    cudaGetSymbolAddress((void**)&a1,   g_a1);
    cudaGetSymbolAddress((void**)&t2,   g_t2);
    cudaGetSymbolAddress((void**)&a2,   g_a2);
    cudaGetSymbolAddress((void**)&ffh,  g_ffh);

    const int att_smem = ATT_SMEM_FLOATS * sizeof(float);   // ~70 KB
    cudaFuncSetAttribute(attn_kernel,
                         cudaFuncAttributeMaxDynamicSharedMemorySize, att_smem);

    dim3 thr(256);
    dim3 gP (DD  / 128, MM / 128);   // N=1024 projections
    dim3 gF1(FFD / 128, MM / 128);   // N=4096 FFN up
    dim3 gA (LL / 64, BB * HH);      // attention

    auto run_mha = [&](int i, const float* xq, const float* xkv,
                       const float* resid, float* dest) {
        sgemm_kernel<false, true ><<<gP, thr>>>(xq,  Wq + (size_t)i * DD * DD, bq + i * DD, q, MM, DD, DD);
        sgemm_kernel<false, true ><<<gP, thr>>>(xkv, Wk + (size_t)i * DD * DD, bk + i * DD, k, MM, DD, DD);
        sgemm_kernel<false, true ><<<gP, thr>>>(xkv, Wv + (size_t)i * DD * DD, bv + i * DD, v, MM, DD, DD);
        attn_kernel<<<gA, thr, att_smem>>>(q, k, v, mask, pad, ctx);
        sgemm_kernel<false, false><<<gP, thr>>>(ctx, Wo + (size_t)i * DD * DD, nullptr, proj, MM, DD, DD);
        ln_residual_kernel<<<MM, thr>>>(resid, proj, lng + i * DD, lnb + i * DD, dest);
    };

    run_mha(0, T,  T,  T,  t1);   // self-attn time
    run_mha(1, A,  A,  A,  a1);   // self-attn act
    run_mha(2, t1, a1, t1, t2);   // cross: T queries A
    run_mha(3, a1, t2, a1, a2);   // cross: A queries T2

    // FFNs (no residual/norm after, per reference)
    sgemm_kernel<true,  true><<<gF1, thr>>>(t2, fW1, fb1, ffh, MM, FFD, DD);
    sgemm_kernel<false, true><<<gP,  thr>>>(ffh, fW2, fb2, out, MM, DD, FFD);
    sgemm_kernel<true,  true><<<gF1, thr>>>(a2, fW1 + (size_t)DD * FFD, fb1 + FFD, ffh, MM, FFD, DD);
    sgemm_kernel<false, true><<<gP,  thr>>>(ffh, fW2 + (size_t)FFD * DD, fb2 + DD,
                                            out + (size_t)MM * DD, MM, DD, FFD);
}

// round 4
// speedup vs baseline: 1.8597x; 1.8597x over previous
#include <cuda_runtime.h>
#include <cstdint>
#include <math.h>

// Problem constants
#define BB   4
#define LL   1024
#define DD   1024
#define HH   16
#define HDIM 64
#define FFD  4096
#define MM   (BB * LL)   // 4096 rows

// ---------------------------------------------------------------------------
// Scratch (static __device__ arrays; no allocation allowed)
// ---------------------------------------------------------------------------
__device__ float g_q   [MM * DD];
__device__ float g_k   [MM * DD];
__device__ float g_v   [MM * DD];
__device__ float g_ctx [MM * DD];
__device__ float g_proj[MM * DD];
__device__ float g_t1  [MM * DD];
__device__ float g_a1  [MM * DD];
__device__ float g_t2  [MM * DD];
__device__ float g_a2  [MM * DD];
__device__ float g_ffh [MM * FFD];

// ---------------------------------------------------------------------------
// TF32 tensor-core GEMM: C[M,N] = A[M,K] @ B[K,N] (+bias) (+relu).
// 128x128 CTA tile, BK=32, 256 threads (8 warps, 4x2 warp grid, 32x64/warp),
// mma.sync.m16n8k8 tf32, cp.async double-buffered pipeline.
// M,N multiples of 128; K multiple of 32.
// ---------------------------------------------------------------------------
#define GBM 128
#define GBN 128
#define GBK 32
#define ASTR 36            // As row stride (floats): 36 mod 32 = 4 -> conflict-free frags
#define BSTR 136           // Bs row stride (floats): 136 mod 32 = 8 -> conflict-free frags
#define A_STAGE (GBM * ASTR)       // 4608 floats
#define B_STAGE (GBK * BSTR)       // 4352 floats
#define GEMM_SMEM_BYTES (2 * (A_STAGE + B_STAGE) * 4)   // 71680 B

__device__ __forceinline__ uint32_t f2tf32(float x) {
    uint32_t u;
    asm("cvt.rna.tf32.f32 %0, %1;" : "=r"(u) : "f"(x));
    return u;
}

template <bool RELU, bool BIAS>
__global__ void __launch_bounds__(256) gemm_tf32(
    const float* __restrict__ A, const float* __restrict__ Bm,
    const float* __restrict__ bias, float* __restrict__ C,
    int M, int N, int K)
{
    extern __shared__ float sm[];
    float* As = sm;                 // [2][GBM][ASTR]
    float* Bs = sm + 2 * A_STAGE;   // [2][GBK][BSTR]

    const int tid  = threadIdx.x;
    const int bm   = blockIdx.y * GBM;
    const int bn   = blockIdx.x * GBN;
    const int wid  = tid >> 5;
    const int lane = tid & 31;
    const int g    = lane >> 2;     // 0..7
    const int t    = lane & 3;      // 0..3
    const int wm   = (wid & 3) * 32;    // warp M offset
    const int wn   = (wid >> 2) * 64;   // warp N offset

    const uint32_t sAs = (uint32_t)__cvta_generic_to_shared(As);
    const uint32_t sBs = (uint32_t)__cvta_generic_to_shared(Bs);

    // per-thread load coords (4 x 16B each for A and B per stage)
    const int a_r  = tid >> 1;                 // with i*128 offset below: rows 0..127
    const int nk = K / GBK;

    // ---- issue one stage of cp.async loads ----
    auto load_stage = [&](int stage, int k0) {
#pragma unroll
        for (int i = 0; i < 4; i++) {
            int id = tid + i * 256;            // 0..1023
            int r  = id >> 3;                  // 0..127
            int kv = (id & 7) << 2;            // 0,4,..28
            uint32_t dst = sAs + ((stage * A_STAGE + r * ASTR + kv) << 2);
            const float* src = A + (size_t)(bm + r) * K + k0 + kv;
            asm volatile("cp.async.cg.shared.global [%0], [%1], 16;\n"
                         :: "r"(dst), "l"(src));
        }
#pragma unroll
        for (int i = 0; i < 4; i++) {
            int id = tid + i * 256;            // 0..1023
            int r  = id >> 5;                  // 0..31
            int nv = (id & 31) << 2;           // 0..124
            uint32_t dst = sBs + ((stage * B_STAGE + r * BSTR + nv) << 2);
            const float* src = Bm + (size_t)(k0 + r) * N + bn + nv;
            asm volatile("cp.async.cg.shared.global [%0], [%1], 16;\n"
                         :: "r"(dst), "l"(src));
        }
        asm volatile("cp.async.commit_group;\n");
    };

    float acc[2][8][4];
#pragma unroll
    for (int mi = 0; mi < 2; mi++)
#pragma unroll
        for (int ni = 0; ni < 8; ni++)
#pragma unroll
            for (int e = 0; e < 4; e++) acc[mi][ni][e] = 0.f;

    load_stage(0, 0);

    for (int kt = 0; kt < nk; kt++) {
        asm volatile("cp.async.wait_group 0;\n");
        __syncthreads();
        const int cur = kt & 1;
        if (kt + 1 < nk) load_stage((kt + 1) & 1, (kt + 1) * GBK);

        const float* Asc = As + cur * A_STAGE;
        const float* Bsc = Bs + cur * B_STAGE;

#pragma unroll
        for (int kk = 0; kk < GBK; kk += 8) {
            uint32_t af[2][4], bf[8][2];
#pragma unroll
            for (int mi = 0; mi < 2; mi++) {
                const int r = wm + mi * 16 + g;
                // m16n8k8 tf32 A frag: a0=(g,t) a1=(g+8,t) a2=(g,t+4) a3=(g+8,t+4)
                af[mi][0] = f2tf32(Asc[r * ASTR + kk + t]);
                af[mi][1] = f2tf32(Asc[(r + 8) * ASTR + kk + t]);
                af[mi][2] = f2tf32(Asc[r * ASTR + kk + t + 4]);
                af[mi][3] = f2tf32(Asc[(r + 8) * ASTR + kk + t + 4]);
            }
#pragma unroll
            for (int ni = 0; ni < 8; ni++) {
                const int c = wn + ni * 8 + g;
                // B frag: b0=(k=t, n=g) b1=(k=t+4, n=g)
                bf[ni][0] = f2tf32(Bsc[(kk + t) * BSTR + c]);
                bf[ni][1] = f2tf32(Bsc[(kk + t + 4) * BSTR + c]);
            }
#pragma unroll
            for (int mi = 0; mi < 2; mi++)
#pragma unroll
                for (int ni = 0; ni < 8; ni++) {
                    float* d = acc[mi][ni];
                    asm volatile(
                        "mma.sync.aligned.m16n8k8.row.col.f32.tf32.tf32.f32 "
                        "{%0,%1,%2,%3}, {%4,%5,%6,%7}, {%8,%9}, {%0,%1,%2,%3};\n"
                        : "+f"(d[0]), "+f"(d[1]), "+f"(d[2]), "+f"(d[3])
                        : "r"(af[mi][0]), "r"(af[mi][1]), "r"(af[mi][2]), "r"(af[mi][3]),
                          "r"(bf[ni][0]), "r"(bf[ni][1]));
                }
        }
    }

    // Epilogue: c0=(g,2t) c1=(g,2t+1) c2=(g+8,2t) c3=(g+8,2t+1)
#pragma unroll
    for (int mi = 0; mi < 2; mi++) {
#pragma unroll
        for (int ni = 0; ni < 8; ni++) {
            const int row = bm + wm + mi * 16 + g;
            const int col = bn + wn + ni * 8 + (t << 1);
            float v0 = acc[mi][ni][0], v1 = acc[mi][ni][1];
            float v2 = acc[mi][ni][2], v3 = acc[mi][ni][3];
            if (BIAS) {
                const float b0 = bias[col], b1 = bias[col + 1];
                v0 += b0; v1 += b1; v2 += b0; v3 += b1;
            }
            if (RELU) {
                v0 = fmaxf(v0, 0.f); v1 = fmaxf(v1, 0.f);
                v2 = fmaxf(v2, 0.f); v3 = fmaxf(v3, 0.f);
            }
            *(float2*)&C[(size_t)row * N + col]       = make_float2(v0, v1);
            *(float2*)&C[(size_t)(row + 8) * N + col] = make_float2(v2, v3);
        }
    }
}

// ---------------------------------------------------------------------------
// Fused attention (flash-style, fp32) — unchanged from round 1.
// ---------------------------------------------------------------------------
#define SATT 68
#define ATT_SMEM_FLOATS (4 * 64 * SATT + 64)

__global__ void __launch_bounds__(256) attn_kernel(
    const float* __restrict__ Qb, const float* __restrict__ Kb,
    const float* __restrict__ Vb, const float* __restrict__ mask,
    const int* __restrict__ pad, float* __restrict__ ctx)
{
    extern __shared__ float sm[];
    float* Qs   = sm;
    float* Ks   = Qs + 64 * SATT;
    float* Vs   = Ks + 64 * SATT;
    float* Ps   = Vs + 64 * SATT;
    float* pads = Ps + 64 * SATT;

    const int b  = blockIdx.y >> 4;
    const int h  = blockIdx.y & 15;
    const int q0 = blockIdx.x * 64;
    const int tid = threadIdx.x;
    const int tr = tid >> 4;
    const int tc = tid & 15;

    for (int i = tid; i < 64 * 16; i += 256) {
        int r = i >> 4, c = (i & 15) << 2;
        *(float4*)&Qs[r * SATT + c] =
            *(const float4*)&Qb[(size_t)(b * LL + q0 + r) * DD + h * HDIM + c];
    }

    float acc[4][4];
    float mrow[4], lrow[4];
#pragma unroll
    for (int i = 0; i < 4; i++) {
        mrow[i] = -1e30f;
        lrow[i] = 0.f;
#pragma unroll
        for (int j = 0; j < 4; j++) acc[i][j] = 0.f;
    }

    for (int kt = 0; kt < LL / 64; kt++) {
        const int k0 = kt * 64;
        __syncthreads();
        for (int i = tid; i < 64 * 16; i += 256) {
            int r = i >> 4, c = (i & 15) << 2;
            size_t go = (size_t)(b * LL + k0 + r) * DD + h * HDIM + c;
            *(float4*)&Ks[r * SATT + c] = *(const float4*)&Kb[go];
            *(float4*)&Vs[r * SATT + c] = *(const float4*)&Vb[go];
        }
        if (tid < 64) pads[tid] = (float)pad[b * LL + k0 + tid];
        __syncthreads();

        float s[4][4];
#pragma unroll
        for (int i = 0; i < 4; i++)
#pragma unroll
            for (int j = 0; j < 4; j++) s[i][j] = 0.f;

#pragma unroll
        for (int d = 0; d < HDIM; d += 4) {
            float4 q4[4], k4[4];
#pragma unroll
            for (int i = 0; i < 4; i++) q4[i] = *(float4*)&Qs[(tr + 16 * i) * SATT + d];
#pragma unroll
            for (int j = 0; j < 4; j++) k4[j] = *(float4*)&Ks[(tc + 16 * j) * SATT + d];
#pragma unroll
            for (int i = 0; i < 4; i++)
#pragma unroll
                for (int j = 0; j < 4; j++)
                    s[i][j] += q4[i].x * k4[j].x + q4[i].y * k4[j].y +
                               q4[i].z * k4[j].z + q4[i].w * k4[j].w;
        }

#pragma unroll
        for (int i = 0; i < 4; i++) {
            const int qr = q0 + tr + 16 * i;
            float sv[4];
#pragma unroll
            for (int j = 0; j < 4; j++) {
                const int kc = k0 + tc + 16 * j;
                sv[j] = s[i][j] * 0.125f + mask[(size_t)qr * LL + kc] + pads[tc + 16 * j];
            }
            float rm = fmaxf(fmaxf(sv[0], sv[1]), fmaxf(sv[2], sv[3]));
#pragma unroll
            for (int o = 8; o >= 1; o >>= 1)
                rm = fmaxf(rm, __shfl_xor_sync(0xffffffffu, rm, o));
            const float mnew = fmaxf(mrow[i], rm);
            const float corr = __expf(mrow[i] - mnew);
            float rs = 0.f;
#pragma unroll
            for (int j = 0; j < 4; j++) {
                float p = __expf(sv[j] - mnew);
                Ps[(tr + 16 * i) * SATT + tc + 16 * j] = p;
                rs += p;
            }
#pragma unroll
            for (int o = 8; o >= 1; o >>= 1)
                rs += __shfl_xor_sync(0xffffffffu, rs, o);
            lrow[i] = lrow[i] * corr + rs;
            mrow[i] = mnew;
#pragma unroll
            for (int j = 0; j < 4; j++) acc[i][j] *= corr;
        }
        __syncthreads();

#pragma unroll
        for (int k = 0; k < 64; k += 4) {
            float p4[4][4];
#pragma unroll
            for (int i = 0; i < 4; i++)
                *(float4*)p4[i] = *(float4*)&Ps[(tr + 16 * i) * SATT + k];
#pragma unroll
            for (int kk = 0; kk < 4; kk++) {
                float4 v4 = *(float4*)&Vs[(k + kk) * SATT + (tc << 2)];
#pragma unroll
                for (int i = 0; i < 4; i++) {
                    acc[i][0] = fmaf(p4[i][kk], v4.x, acc[i][0]);
                    acc[i][1] = fmaf(p4[i][kk], v4.y, acc[i][1]);
                    acc[i][2] = fmaf(p4[i][kk], v4.z, acc[i][2]);
                    acc[i][3] = fmaf(p4[i][kk], v4.w, acc[i][3]);
                }
            }
        }
    }

#pragma unroll
    for (int i = 0; i < 4; i++) {
        const float inv = 1.f / lrow[i];
        float4 o;
        o.x = acc[i][0] * inv;
        o.y = acc[i][1] * inv;
        o.z = acc[i][2] * inv;
        o.w = acc[i][3] * inv;
        *(float4*)&ctx[(size_t)(b * LL + q0 + tr + 16 * i) * DD + h * HDIM + (tc << 2)] = o;
    }
}

// ---------------------------------------------------------------------------
// out = LayerNorm(x + r) * g + b
// ---------------------------------------------------------------------------
__global__ void __launch_bounds__(256) ln_residual_kernel(
    const float* __restrict__ x, const float* __restrict__ r,
    const float* __restrict__ g, const float* __restrict__ be,
    float* __restrict__ out)
{
    __shared__ float red[8];
    const int row = blockIdx.x;
    const int t = threadIdx.x;

    const float4 a = ((const float4*)(x + (size_t)row * DD))[t];
    const float4 c = ((const float4*)(r + (size_t)row * DD))[t];
    float4 v = make_float4(a.x + c.x, a.y + c.y, a.z + c.z, a.w + c.w);

    float s = v.x + v.y + v.z + v.w;
#pragma unroll
    for (int o = 16; o >= 1; o >>= 1) s += __shfl_xor_sync(0xffffffffu, s, o);
    if ((t & 31) == 0) red[t >> 5] = s;
    __syncthreads();
    float tot = red[0] + red[1] + red[2] + red[3] + red[4] + red[5] + red[6] + red[7];
    const float mean = tot * (1.0f / DD);

    const float dx0 = v.x - mean, dx1 = v.y - mean, dx2 = v.z - mean, dx3 = v.w - mean;
    float sq = dx0 * dx0 + dx1 * dx1 + dx2 * dx2 + dx3 * dx3;
#pragma unroll
    for (int o = 16; o >= 1; o >>= 1) sq += __shfl_xor_sync(0xffffffffu, sq, o);
    __syncthreads();
    if ((t & 31) == 0) red[t >> 5] = sq;
    __syncthreads();
    float var = (red[0] + red[1] + red[2] + red[3] + red[4] + red[5] + red[6] + red[7]) * (1.0f / DD);
    const float rstd = rsqrtf(var + 1e-5f);

    const float4 gg = ((const float4*)g)[t];
    const float4 bb = ((const float4*)be)[t];
    float4 o;
    o.x = dx0 * rstd * gg.x + bb.x;
    o.y = dx1 * rstd * gg.y + bb.y;
    o.z = dx2 * rstd * gg.z + bb.z;
    o.w = dx3 * rstd * gg.w + bb.w;
    ((float4*)(out + (size_t)row * DD))[t] = o;
}

// ---------------------------------------------------------------------------
// Launch
// ---------------------------------------------------------------------------
extern "C" void kernel_launch(void* const* d_in, const int* in_sizes, int n_in,
                              void* d_out, int out_size)
{
    const float* T    = (const float*)d_in[0];
    const float* A    = (const float*)d_in[1];
    const float* mask = (const float*)d_in[2];
    const int*   pad  = (const int*)  d_in[3];
    const float* Wq   = (const float*)d_in[4];
    const float* bq   = (const float*)d_in[5];
    const float* Wk   = (const float*)d_in[6];
    const float* bk   = (const float*)d_in[7];
    const float* Wv   = (const float*)d_in[8];
    const float* bv   = (const float*)d_in[9];
    const float* Wo   = (const float*)d_in[10];
    const float* fW1  = (const float*)d_in[11];
    const float* fb1  = (const float*)d_in[12];
    const float* fW2  = (const float*)d_in[13];
    const float* fb2  = (const float*)d_in[14];
    const float* lng  = (const float*)d_in[15];
    const float* lnb  = (const float*)d_in[16];
    float* out = (float*)d_out;

    float *q, *k, *v, *ctx, *proj, *t1, *a1, *t2, *a2, *ffh;
    cudaGetSymbolAddress((void**)&q,    g_q);
    cudaGetSymbolAddress((void**)&k,    g_k);
    cudaGetSymbolAddress((void**)&v,    g_v);
    cudaGetSymbolAddress((void**)&ctx,  g_ctx);
    cudaGetSymbolAddress((void**)&proj, g_proj);
    cudaGetSymbolAddress((void**)&t1,   g_t1);
    cudaGetSymbolAddress((void**)&a1,   g_a1);
    cudaGetSymbolAddress((void**)&t2,   g_t2);
    cudaGetSymbolAddress((void**)&a2,   g_a2);
    cudaGetSymbolAddress((void**)&ffh,  g_ffh);

    const int att_smem = ATT_SMEM_FLOATS * sizeof(float);
    cudaFuncSetAttribute(attn_kernel,
                         cudaFuncAttributeMaxDynamicSharedMemorySize, att_smem);
    cudaFuncSetAttribute(gemm_tf32<false, true >,
                         cudaFuncAttributeMaxDynamicSharedMemorySize, GEMM_SMEM_BYTES);
    cudaFuncSetAttribute(gemm_tf32<false, false>,
                         cudaFuncAttributeMaxDynamicSharedMemorySize, GEMM_SMEM_BYTES);
    cudaFuncSetAttribute(gemm_tf32<true,  true >,
                         cudaFuncAttributeMaxDynamicSharedMemorySize, GEMM_SMEM_BYTES);

    dim3 thr(256);
    dim3 gP (DD  / GBN, MM / GBM);   // N=1024
    dim3 gF1(FFD / GBN, MM / GBM);   // N=4096
    dim3 gA (LL / 64, BB * HH);

    auto run_mha = [&](int i, const float* xq, const float* xkv,
                       const float* resid, float* dest) {
        gemm_tf32<false, true ><<<gP, thr, GEMM_SMEM_BYTES>>>(xq,  Wq + (size_t)i * DD * DD, bq + i * DD, q, MM, DD, DD);
        gemm_tf32<false, true ><<<gP, thr, GEMM_SMEM_BYTES>>>(xkv, Wk + (size_t)i * DD * DD, bk + i * DD, k, MM, DD, DD);
        gemm_tf32<false, true ><<<gP, thr, GEMM_SMEM_BYTES>>>(xkv, Wv + (size_t)i * DD * DD, bv + i * DD, v, MM, DD, DD);
        attn_kernel<<<gA, thr, att_smem>>>(q, k, v, mask, pad, ctx);
        gemm_tf32<false, false><<<gP, thr, GEMM_SMEM_BYTES>>>(ctx, Wo + (size_t)i * DD * DD, nullptr, proj, MM, DD, DD);
        ln_residual_kernel<<<MM, thr>>>(resid, proj, lng + i * DD, lnb + i * DD, dest);
    };

    run_mha(0, T,  T,  T,  t1);
    run_mha(1, A,  A,  A,  a1);
    run_mha(2, t1, a1, t1, t2);
    run_mha(3, a1, t2, a1, a2);

    gemm_tf32<true,  true><<<gF1, thr, GEMM_SMEM_BYTES>>>(t2, fW1, fb1, ffh, MM, FFD, DD);
    gemm_tf32<false, true><<<gP,  thr, GEMM_SMEM_BYTES>>>(ffh, fW2, fb2, out, MM, DD, FFD);
    gemm_tf32<true,  true><<<gF1, thr, GEMM_SMEM_BYTES>>>(a2, fW1 + (size_t)DD * FFD, fb1 + FFD, ffh, MM, FFD, DD);
    gemm_tf32<false, true><<<gP,  thr, GEMM_SMEM_BYTES>>>(ffh, fW2 + (size_t)FFD * DD, fb2 + DD,
                                                          out + (size_t)MM * DD, MM, DD, FFD);
}

// round 9
// speedup vs baseline: 2.4220x; 1.3024x over previous
#include <cuda_runtime.h>
#include <cstdint>
#include <math.h>

// Problem constants
#define BB   4
#define LL   1024
#define DD   1024
#define HH   16
#define HDIM 64
#define FFD  4096
#define MM   (BB * LL)   // 4096 rows

// ---------------------------------------------------------------------------
// Scratch (static __device__ arrays; no allocation allowed)
// ---------------------------------------------------------------------------
__device__ float g_q   [MM * DD];
__device__ float g_k   [MM * DD];
__device__ float g_v   [MM * DD];
__device__ float g_ctx [MM * DD];
__device__ float g_proj[MM * DD];
__device__ float g_t1  [MM * DD];
__device__ float g_a1  [MM * DD];
__device__ float g_t2  [MM * DD];
__device__ float g_a2  [MM * DD];
__device__ float g_ffh [MM * FFD];

__device__ __forceinline__ uint32_t f2tf32(float x) {
    uint32_t u;
    asm("cvt.rna.tf32.f32 %0, %1;" : "=r"(u) : "f"(x));
    return u;
}

// ---------------------------------------------------------------------------
// TF32 tensor-core GEMM (unchanged from round 3 — known good, 117 TF/s).
// ---------------------------------------------------------------------------
#define GBM 128
#define GBN 128
#define GBK 32
#define ASTR 36
#define BSTR 136
#define A_STAGE (GBM * ASTR)
#define B_STAGE (GBK * BSTR)
#define GEMM_SMEM_BYTES (2 * (A_STAGE + B_STAGE) * 4)

template <bool RELU, bool BIAS>
__global__ void __launch_bounds__(256) gemm_tf32(
    const float* __restrict__ A, const float* __restrict__ Bm,
    const float* __restrict__ bias, float* __restrict__ C,
    int M, int N, int K)
{
    extern __shared__ float sm[];
    float* As = sm;
    float* Bs = sm + 2 * A_STAGE;

    const int tid  = threadIdx.x;
    const int bm   = blockIdx.y * GBM;
    const int bn   = blockIdx.x * GBN;
    const int wid  = tid >> 5;
    const int lane = tid & 31;
    const int g    = lane >> 2;
    const int t    = lane & 3;
    const int wm   = (wid & 3) * 32;
    const int wn   = (wid >> 2) * 64;

    const uint32_t sAs = (uint32_t)__cvta_generic_to_shared(As);
    const uint32_t sBs = (uint32_t)__cvta_generic_to_shared(Bs);
    const int nk = K / GBK;

    auto load_stage = [&](int stage, int k0) {
#pragma unroll
        for (int i = 0; i < 4; i++) {
            int id = tid + i * 256;
            int r  = id >> 3;
            int kv = (id & 7) << 2;
            uint32_t dst = sAs + ((stage * A_STAGE + r * ASTR + kv) << 2);
            const float* src = A + (size_t)(bm + r) * K + k0 + kv;
            asm volatile("cp.async.cg.shared.global [%0], [%1], 16;\n"
                         :: "r"(dst), "l"(src));
        }
#pragma unroll
        for (int i = 0; i < 4; i++) {
            int id = tid + i * 256;
            int r  = id >> 5;
            int nv = (id & 31) << 2;
            uint32_t dst = sBs + ((stage * B_STAGE + r * BSTR + nv) << 2);
            const float* src = Bm + (size_t)(k0 + r) * N + bn + nv;
            asm volatile("cp.async.cg.shared.global [%0], [%1], 16;\n"
                         :: "r"(dst), "l"(src));
        }
        asm volatile("cp.async.commit_group;\n");
    };

    float acc[2][8][4];
#pragma unroll
    for (int mi = 0; mi < 2; mi++)
#pragma unroll
        for (int ni = 0; ni < 8; ni++)
#pragma unroll
            for (int e = 0; e < 4; e++) acc[mi][ni][e] = 0.f;

    load_stage(0, 0);

    for (int kt = 0; kt < nk; kt++) {
        asm volatile("cp.async.wait_group 0;\n");
        __syncthreads();
        const int cur = kt & 1;
        if (kt + 1 < nk) load_stage((kt + 1) & 1, (kt + 1) * GBK);

        const float* Asc = As + cur * A_STAGE;
        const float* Bsc = Bs + cur * B_STAGE;

#pragma unroll
        for (int kk = 0; kk < GBK; kk += 8) {
            uint32_t af[2][4], bf[8][2];
#pragma unroll
            for (int mi = 0; mi < 2; mi++) {
                const int r = wm + mi * 16 + g;
                af[mi][0] = f2tf32(Asc[r * ASTR + kk + t]);
                af[mi][1] = f2tf32(Asc[(r + 8) * ASTR + kk + t]);
                af[mi][2] = f2tf32(Asc[r * ASTR + kk + t + 4]);
                af[mi][3] = f2tf32(Asc[(r + 8) * ASTR + kk + t + 4]);
            }
#pragma unroll
            for (int ni = 0; ni < 8; ni++) {
                const int c = wn + ni * 8 + g;
                bf[ni][0] = f2tf32(Bsc[(kk + t) * BSTR + c]);
                bf[ni][1] = f2tf32(Bsc[(kk + t + 4) * BSTR + c]);
            }
#pragma unroll
            for (int mi = 0; mi < 2; mi++)
#pragma unroll
                for (int ni = 0; ni < 8; ni++) {
                    float* d = acc[mi][ni];
                    asm volatile(
                        "mma.sync.aligned.m16n8k8.row.col.f32.tf32.tf32.f32 "
                        "{%0,%1,%2,%3}, {%4,%5,%6,%7}, {%8,%9}, {%0,%1,%2,%3};\n"
                        : "+f"(d[0]), "+f"(d[1]), "+f"(d[2]), "+f"(d[3])
                        : "r"(af[mi][0]), "r"(af[mi][1]), "r"(af[mi][2]), "r"(af[mi][3]),
                          "r"(bf[ni][0]), "r"(bf[ni][1]));
                }
        }
    }

#pragma unroll
    for (int mi = 0; mi < 2; mi++) {
#pragma unroll
        for (int ni = 0; ni < 8; ni++) {
            const int row = bm + wm + mi * 16 + g;
            const int col = bn + wn + ni * 8 + (t << 1);
            float v0 = acc[mi][ni][0], v1 = acc[mi][ni][1];
            float v2 = acc[mi][ni][2], v3 = acc[mi][ni][3];
            if (BIAS) {
                const float b0 = bias[col], b1 = bias[col + 1];
                v0 += b0; v1 += b1; v2 += b0; v3 += b1;
            }
            if (RELU) {
                v0 = fmaxf(v0, 0.f); v1 = fmaxf(v1, 0.f);
                v2 = fmaxf(v2, 0.f); v3 = fmaxf(v3, 0.f);
            }
            *(float2*)&C[(size_t)row * N + col]       = make_float2(v0, v1);
            *(float2*)&C[(size_t)(row + 8) * N + col] = make_float2(v2, v3);
        }
    }
}

// ---------------------------------------------------------------------------
// TF32 tensor-core flash attention — FIXED decomposition.
// Grid (LL/128, B*H); 256 threads = 8 warps; warp w owns rows [w*16, w*16+16)
// and the FULL 128-key width -> softmax stats are warp-local, P is
// warp-private (row-disjoint) in smem.
// Smem strides: Q/K 68 (mod 32=4), V 72 (mod 32=8), P 132 (mod 32=4) — all
// fragment access patterns conflict-free.
// ---------------------------------------------------------------------------
#define ATQ 68
#define ATV 72
#define ATP 132
#define AK_OFF   (128 * ATQ)
#define AV_OFF   (AK_OFF + 128 * ATQ)
#define AP_OFF   (AV_OFF + 128 * ATV)
#define APAD_OFF (AP_OFF + 128 * ATP)
#define ATT_SMEM_BYTES ((APAD_OFF + 128) * 4)   // 174,592 B

__global__ void __launch_bounds__(256) attn_tc_kernel(
    const float* __restrict__ Qb, const float* __restrict__ Kb,
    const float* __restrict__ Vb, const float* __restrict__ mask,
    const int* __restrict__ pad, float* __restrict__ ctx)
{
    extern __shared__ float sm[];
    float* Qs   = sm;
    float* Ks   = sm + AK_OFF;
    float* Vs   = sm + AV_OFF;
    float* Ps   = sm + AP_OFF;
    float* pads = sm + APAD_OFF;

    const int b   = blockIdx.y >> 4;
    const int h   = blockIdx.y & 15;
    const int q0  = blockIdx.x * 128;
    const int tid = threadIdx.x;
    const int wid = tid >> 5;
    const int lane = tid & 31;
    const int g   = lane >> 2;      // 0..7
    const int t   = lane & 3;       // 0..3
    const int wm  = wid * 16;       // warp's 16 rows

    const uint32_t sQ = (uint32_t)__cvta_generic_to_shared(Qs);
    const uint32_t sK = (uint32_t)__cvta_generic_to_shared(Ks);
    const uint32_t sV = (uint32_t)__cvta_generic_to_shared(Vs);

    // Load Q tile [128 rows x 64 dims]
#pragma unroll
    for (int i = 0; i < 8; i++) {
        int id = tid + i * 256;
        int r = id >> 4, c = (id & 15) << 2;
        uint32_t dst = sQ + ((r * ATQ + c) << 2);
        const float* src = Qb + (size_t)(b * LL + q0 + r) * DD + h * HDIM + c;
        asm volatile("cp.async.cg.shared.global [%0], [%1], 16;\n" :: "r"(dst), "l"(src));
    }
    asm volatile("cp.async.commit_group;\n");

    // O accumulators: 8 n-tiles (64 dims); softmax state for rows g, g+8
    float o[8][4];
    float mrow[2] = {-1e30f, -1e30f}, lrow[2] = {0.f, 0.f};
#pragma unroll
    for (int ni = 0; ni < 8; ni++)
#pragma unroll
        for (int e = 0; e < 4; e++) o[ni][e] = 0.f;

    for (int kt = 0; kt < LL / 128; kt++) {
        const int k0 = kt * 128;
        __syncthreads();   // everyone done reading Ks/Vs of the previous tile

        // Load K, V tiles [128 x 64]
#pragma unroll
        for (int i = 0; i < 8; i++) {
            int id = tid + i * 256;
            int r = id >> 4, c = (id & 15) << 2;
            size_t go = (size_t)(b * LL + k0 + r) * DD + h * HDIM + c;
            uint32_t dk = sK + ((r * ATQ + c) << 2);
            uint32_t dv = sV + ((r * ATV + c) << 2);
            asm volatile("cp.async.cg.shared.global [%0], [%1], 16;\n" :: "r"(dk), "l"(Kb + go));
            asm volatile("cp.async.cg.shared.global [%0], [%1], 16;\n" :: "r"(dv), "l"(Vb + go));
        }
        if (tid < 128) pads[tid] = (float)pad[b * LL + k0 + tid];
        asm volatile("cp.async.commit_group;\n");
        asm volatile("cp.async.wait_group 0;\n");
        __syncthreads();

        // ---- S[16 x 128] = Q @ K^T ----
        float s[16][4];
#pragma unroll
        for (int ni = 0; ni < 16; ni++)
#pragma unroll
            for (int e = 0; e < 4; e++) s[ni][e] = 0.f;

#pragma unroll
        for (int kk = 0; kk < HDIM; kk += 8) {
            uint32_t af[4], bf[16][2];
            af[0] = f2tf32(Qs[(wm + g) * ATQ + kk + t]);
            af[1] = f2tf32(Qs[(wm + g + 8) * ATQ + kk + t]);
            af[2] = f2tf32(Qs[(wm + g) * ATQ + kk + t + 4]);
            af[3] = f2tf32(Qs[(wm + g + 8) * ATQ + kk + t + 4]);
#pragma unroll
            for (int ni = 0; ni < 16; ni++) {
                const int key = ni * 8 + g;
                bf[ni][0] = f2tf32(Ks[key * ATQ + kk + t]);
                bf[ni][1] = f2tf32(Ks[key * ATQ + kk + t + 4]);
            }
#pragma unroll
            for (int ni = 0; ni < 16; ni++) {
                float* d = s[ni];
                asm volatile(
                    "mma.sync.aligned.m16n8k8.row.col.f32.tf32.tf32.f32 "
                    "{%0,%1,%2,%3}, {%4,%5,%6,%7}, {%8,%9}, {%0,%1,%2,%3};\n"
                    : "+f"(d[0]), "+f"(d[1]), "+f"(d[2]), "+f"(d[3])
                    : "r"(af[0]), "r"(af[1]), "r"(af[2]), "r"(af[3]),
                      "r"(bf[ni][0]), "r"(bf[ni][1]));
            }
        }

        // ---- online softmax over the FULL 128 keys (warp-local rows) ----
#pragma unroll
        for (int hf = 0; hf < 2; hf++) {
            const int r  = wm + g + hf * 8;
            const int qr = q0 + r;
            float rm = -1e30f;
#pragma unroll
            for (int ni = 0; ni < 16; ni++) {
                const int kcl = ni * 8 + (t << 1);
                const float2 mk = *(const float2*)&mask[(size_t)qr * LL + k0 + kcl];
                float v0 = s[ni][hf * 2 + 0] * 0.125f + mk.x + pads[kcl];
                float v1 = s[ni][hf * 2 + 1] * 0.125f + mk.y + pads[kcl + 1];
                s[ni][hf * 2 + 0] = v0;
                s[ni][hf * 2 + 1] = v1;
                rm = fmaxf(rm, fmaxf(v0, v1));
            }
            rm = fmaxf(rm, __shfl_xor_sync(0xffffffffu, rm, 1));
            rm = fmaxf(rm, __shfl_xor_sync(0xffffffffu, rm, 2));
            const float mnew = fmaxf(mrow[hf], rm);
            const float corr = __expf(mrow[hf] - mnew);
            mrow[hf] = mnew;
            float rs = 0.f;
#pragma unroll
            for (int ni = 0; ni < 16; ni++) {
                float p0 = __expf(s[ni][hf * 2 + 0] - mnew);
                float p1 = __expf(s[ni][hf * 2 + 1] - mnew);
                *(float2*)&Ps[r * ATP + ni * 8 + (t << 1)] = make_float2(p0, p1);
                rs += p0 + p1;
            }
            rs += __shfl_xor_sync(0xffffffffu, rs, 1);
            rs += __shfl_xor_sync(0xffffffffu, rs, 2);
            lrow[hf] = lrow[hf] * corr + rs;
#pragma unroll
            for (int ni = 0; ni < 8; ni++) {
                o[ni][hf * 2 + 0] *= corr;
                o[ni][hf * 2 + 1] *= corr;
            }
        }
        __syncwarp();   // P rows are warp-private; warp-level ordering suffices

        // ---- O[16 x 64] += P @ V ----
#pragma unroll
        for (int kk = 0; kk < 128; kk += 8) {
            uint32_t ap[4], bv[8][2];
            ap[0] = f2tf32(Ps[(wm + g) * ATP + kk + t]);
            ap[1] = f2tf32(Ps[(wm + g + 8) * ATP + kk + t]);
            ap[2] = f2tf32(Ps[(wm + g) * ATP + kk + t + 4]);
            ap[3] = f2tf32(Ps[(wm + g + 8) * ATP + kk + t + 4]);
#pragma unroll
            for (int ni = 0; ni < 8; ni++) {
                const int c = ni * 8 + g;
                bv[ni][0] = f2tf32(Vs[(kk + t) * ATV + c]);
                bv[ni][1] = f2tf32(Vs[(kk + t + 4) * ATV + c]);
            }
#pragma unroll
            for (int ni = 0; ni < 8; ni++) {
                float* d = o[ni];
                asm volatile(
                    "mma.sync.aligned.m16n8k8.row.col.f32.tf32.tf32.f32 "
                    "{%0,%1,%2,%3}, {%4,%5,%6,%7}, {%8,%9}, {%0,%1,%2,%3};\n"
                    : "+f"(d[0]), "+f"(d[1]), "+f"(d[2]), "+f"(d[3])
                    : "r"(ap[0]), "r"(ap[1]), "r"(ap[2]), "r"(ap[3]),
                      "r"(bv[ni][0]), "r"(bv[ni][1]));
            }
        }
    }

    // ---- epilogue ----
    const float inv0 = 1.f / lrow[0];
    const float inv1 = 1.f / lrow[1];
#pragma unroll
    for (int ni = 0; ni < 8; ni++) {
        const int col = h * HDIM + ni * 8 + (t << 1);
        *(float2*)&ctx[(size_t)(b * LL + q0 + wm + g) * DD + col] =
            make_float2(o[ni][0] * inv0, o[ni][1] * inv0);
        *(float2*)&ctx[(size_t)(b * LL + q0 + wm + g + 8) * DD + col] =
            make_float2(o[ni][2] * inv1, o[ni][3] * inv1);
    }
}

// ---------------------------------------------------------------------------
// out = LayerNorm(x + r) * g + b
// ---------------------------------------------------------------------------
__global__ void __launch_bounds__(256) ln_residual_kernel(
    const float* __restrict__ x, const float* __restrict__ r,
    const float* __restrict__ g, const float* __restrict__ be,
    float* __restrict__ out)
{
    __shared__ float red[8];
    const int row = blockIdx.x;
    const int t = threadIdx.x;

    const float4 a = ((const float4*)(x + (size_t)row * DD))[t];
    const float4 c = ((const float4*)(r + (size_t)row * DD))[t];
    float4 v = make_float4(a.x + c.x, a.y + c.y, a.z + c.z, a.w + c.w);

    float s = v.x + v.y + v.z + v.w;
#pragma unroll
    for (int o = 16; o >= 1; o >>= 1) s += __shfl_xor_sync(0xffffffffu, s, o);
    if ((t & 31) == 0) red[t >> 5] = s;
    __syncthreads();
    float tot = red[0] + red[1] + red[2] + red[3] + red[4] + red[5] + red[6] + red[7];
    const float mean = tot * (1.0f / DD);

    const float dx0 = v.x - mean, dx1 = v.y - mean, dx2 = v.z - mean, dx3 = v.w - mean;
    float sq = dx0 * dx0 + dx1 * dx1 + dx2 * dx2 + dx3 * dx3;
#pragma unroll
    for (int o = 16; o >= 1; o >>= 1) sq += __shfl_xor_sync(0xffffffffu, sq, o);
    __syncthreads();
    if ((t & 31) == 0) red[t >> 5] = sq;
    __syncthreads();
    float var = (red[0] + red[1] + red[2] + red[3] + red[4] + red[5] + red[6] + red[7]) * (1.0f / DD);
    const float rstd = rsqrtf(var + 1e-5f);

    const float4 gg = ((const float4*)g)[t];
    const float4 bb = ((const float4*)be)[t];
    float4 ov;
    ov.x = dx0 * rstd * gg.x + bb.x;
    ov.y = dx1 * rstd * gg.y + bb.y;
    ov.z = dx2 * rstd * gg.z + bb.z;
    ov.w = dx3 * rstd * gg.w + bb.w;
    ((float4*)(out + (size_t)row * DD))[t] = ov;
}

// ---------------------------------------------------------------------------
// Launch
// ---------------------------------------------------------------------------
extern "C" void kernel_launch(void* const* d_in, const int* in_sizes, int n_in,
                              void* d_out, int out_size)
{
    const float* T    = (const float*)d_in[0];
    const float* A    = (const float*)d_in[1];
    const float* mask = (const float*)d_in[2];
    const int*   pad  = (const int*)  d_in[3];
    const float* Wq   = (const float*)d_in[4];
    const float* bq   = (const float*)d_in[5];
    const float* Wk   = (const float*)d_in[6];
    const float* bk   = (const float*)d_in[7];
    const float* Wv   = (const float*)d_in[8];
    const float* bv   = (const float*)d_in[9];
    const float* Wo   = (const float*)d_in[10];
    const float* fW1  = (const float*)d_in[11];
    const float* fb1  = (const float*)d_in[12];
    const float* fW2  = (const float*)d_in[13];
    const float* fb2  = (const float*)d_in[14];
    const float* lng  = (const float*)d_in[15];
    const float* lnb  = (const float*)d_in[16];
    float* out = (float*)d_out;

    float *q, *k, *v, *ctx, *proj, *t1, *a1, *t2, *a2, *ffh;
    cudaGetSymbolAddress((void**)&q,    g_q);
    cudaGetSymbolAddress((void**)&k,    g_k);
    cudaGetSymbolAddress((void**)&v,    g_v);
    cudaGetSymbolAddress((void**)&ctx,  g_ctx);
    cudaGetSymbolAddress((void**)&proj, g_proj);
    cudaGetSymbolAddress((void**)&t1,   g_t1);
    cudaGetSymbolAddress((void**)&a1,   g_a1);
    cudaGetSymbolAddress((void**)&t2,   g_t2);
    cudaGetSymbolAddress((void**)&a2,   g_a2);
    cudaGetSymbolAddress((void**)&ffh,  g_ffh);

    cudaFuncSetAttribute(attn_tc_kernel,
                         cudaFuncAttributeMaxDynamicSharedMemorySize, ATT_SMEM_BYTES);
    cudaFuncSetAttribute(gemm_tf32<false, true >,
                         cudaFuncAttributeMaxDynamicSharedMemorySize, GEMM_SMEM_BYTES);
    cudaFuncSetAttribute(gemm_tf32<false, false>,
                         cudaFuncAttributeMaxDynamicSharedMemorySize, GEMM_SMEM_BYTES);
    cudaFuncSetAttribute(gemm_tf32<true,  true >,
                         cudaFuncAttributeMaxDynamicSharedMemorySize, GEMM_SMEM_BYTES);

    dim3 thr(256);
    dim3 gP (DD  / GBN, MM / GBM);
    dim3 gF1(FFD / GBN, MM / GBM);
    dim3 gA (LL / 128, BB * HH);

    auto run_mha = [&](int i, const float* xq, const float* xkv,
                       const float* resid, float* dest) {
        gemm_tf32<false, true ><<<gP, thr, GEMM_SMEM_BYTES>>>(xq,  Wq + (size_t)i * DD * DD, bq + i * DD, q, MM, DD, DD);
        gemm_tf32<false, true ><<<gP, thr, GEMM_SMEM_BYTES>>>(xkv, Wk + (size_t)i * DD * DD, bk + i * DD, k, MM, DD, DD);
        gemm_tf32<false, true ><<<gP, thr, GEMM_SMEM_BYTES>>>(xkv, Wv + (size_t)i * DD * DD, bv + i * DD, v, MM, DD, DD);
        attn_tc_kernel<<<gA, thr, ATT_SMEM_BYTES>>>(q, k, v, mask, pad, ctx);
        gemm_tf32<false, false><<<gP, thr, GEMM_SMEM_BYTES>>>(ctx, Wo + (size_t)i * DD * DD, nullptr, proj, MM, DD, DD);
        ln_residual_kernel<<<MM, thr>>>(resid, proj, lng + i * DD, lnb + i * DD, dest);
    };

    run_mha(0, T,  T,  T,  t1);
    run_mha(1, A,  A,  A,  a1);
    run_mha(2, t1, a1, t1, t2);
    run_mha(3, a1, t2, a1, a2);

    gemm_tf32<true,  true><<<gF1, thr, GEMM_SMEM_BYTES>>>(t2, fW1, fb1, ffh, MM, FFD, DD);
    gemm_tf32<false, true><<<gP,  thr, GEMM_SMEM_BYTES>>>(ffh, fW2, fb2, out, MM, DD, FFD);
    gemm_tf32<true,  true><<<gF1, thr, GEMM_SMEM_BYTES>>>(a2, fW1 + (size_t)DD * FFD, fb1 + FFD, ffh, MM, FFD, DD);
    gemm_tf32<false, true><<<gP,  thr, GEMM_SMEM_BYTES>>>(ffh, fW2 + (size_t)FFD * DD, fb2 + DD,
                                                          out + (size_t)MM * DD, MM, DD, FFD);
}

// round 10
// speedup vs baseline: 2.9784x; 1.2297x over previous
#include <cuda_runtime.h>
#include <cstdint>
#include <math.h>

// Problem constants
#define BB   4
#define LL   1024
#define DD   1024
#define HH   16
#define HDIM 64
#define FFD  4096
#define MM   (BB * LL)   // 4096 rows

// ---------------------------------------------------------------------------
// Scratch (static __device__ arrays; no allocation allowed)
// ---------------------------------------------------------------------------
__device__ float g_q   [MM * DD];
__device__ float g_k   [MM * DD];
__device__ float g_v   [MM * DD];
__device__ float g_ctx [MM * DD];
__device__ float g_proj[MM * DD];
__device__ float g_t1  [MM * DD];
__device__ float g_a1  [MM * DD];
__device__ float g_t2  [MM * DD];
__device__ float g_a2  [MM * DD];
__device__ float g_ffh [MM * FFD];
// tf32-rounded copies (round once at producer, consume raw)
__device__ float g_tr  [MM * DD];
__device__ float g_ar  [MM * DD];
__device__ float g_wq  [4 * DD * DD];
__device__ float g_wk  [4 * DD * DD];
__device__ float g_wv  [4 * DD * DD];
__device__ float g_wo  [4 * DD * DD];
__device__ float g_fw1 [2 * DD * FFD];
__device__ float g_fw2 [2 * FFD * DD];
__device__ float g_padf[BB * LL];

__device__ __forceinline__ uint32_t f2tf32(float x) {
    uint32_t u;
    asm("cvt.rna.tf32.f32 %0, %1;" : "=r"(u) : "f"(x));
    return u;
}
__device__ __forceinline__ float roundtf(float x) {
    return __uint_as_float(f2tf32(x));
}

// ---------------------------------------------------------------------------
// Pre-round: out = tf32_round(in), float4 grid-stride
// ---------------------------------------------------------------------------
__global__ void round_copy_kernel(const float4* __restrict__ in,
                                  float4* __restrict__ out, int n4)
{
    for (int i = blockIdx.x * blockDim.x + threadIdx.x; i < n4;
         i += gridDim.x * blockDim.x) {
        float4 v = in[i];
        v.x = roundtf(v.x); v.y = roundtf(v.y);
        v.z = roundtf(v.z); v.w = roundtf(v.w);
        out[i] = v;
    }
}

__global__ void pad_to_float_kernel(const int* __restrict__ pad,
                                    float* __restrict__ padf, int n)
{
    int i = blockIdx.x * blockDim.x + threadIdx.x;
    if (i < n) padf[i] = (float)pad[i];
}

// ---------------------------------------------------------------------------
// TF32 tensor-core GEMM: inputs pre-rounded to tf32 -> NO cvt in inner loop.
// 128x128 CTA tile, BK=32, 3-stage cp.async pipeline, 2 CTAs/SM.
// ---------------------------------------------------------------------------
#define GBM 128
#define GBN 128
#define GBK 32
#define ASTR 36
#define BSTR 136
#define A_STAGE (GBM * ASTR)          // 4608 floats
#define B_STAGE (GBK * BSTR)          // 4352 floats
#define STG (A_STAGE + B_STAGE)       // 8960 floats
#define GEMM_SMEM_BYTES (3 * STG * 4) // 107,520 B

template <bool RELU, bool BIAS, bool ROUND>
__global__ void __launch_bounds__(256, 2) gemm_tf32(
    const float* __restrict__ A, const float* __restrict__ Bm,
    const float* __restrict__ bias, float* __restrict__ C,
    int M, int N, int K)
{
    extern __shared__ float sm[];

    const int tid  = threadIdx.x;
    const int bm   = blockIdx.y * GBM;
    const int bn   = blockIdx.x * GBN;
    const int wid  = tid >> 5;
    const int lane = tid & 31;
    const int g    = lane >> 2;
    const int t    = lane & 3;
    const int wm   = (wid & 3) * 32;
    const int wn   = (wid >> 2) * 64;

    const uint32_t sbase = (uint32_t)__cvta_generic_to_shared(sm);
    const int nk = K / GBK;

    auto load_stage = [&](int slot, int k0) {
#pragma unroll
        for (int i = 0; i < 4; i++) {
            int id = tid + i * 256;
            int r  = id >> 3;
            int kv = (id & 7) << 2;
            uint32_t dst = sbase + ((slot * STG + r * ASTR + kv) << 2);
            const float* src = A + (size_t)(bm + r) * K + k0 + kv;
            asm volatile("cp.async.cg.shared.global [%0], [%1], 16;\n"
                         :: "r"(dst), "l"(src));
        }
#pragma unroll
        for (int i = 0; i < 4; i++) {
            int id = tid + i * 256;
            int r  = id >> 5;
            int nv = (id & 31) << 2;
            uint32_t dst = sbase + ((slot * STG + A_STAGE + r * BSTR + nv) << 2);
            const float* src = Bm + (size_t)(k0 + r) * N + bn + nv;
            asm volatile("cp.async.cg.shared.global [%0], [%1], 16;\n"
                         :: "r"(dst), "l"(src));
        }
    };

    float acc[2][8][4];
#pragma unroll
    for (int mi = 0; mi < 2; mi++)
#pragma unroll
        for (int ni = 0; ni < 8; ni++)
#pragma unroll
            for (int e = 0; e < 4; e++) acc[mi][ni][e] = 0.f;

    load_stage(0, 0);
    asm volatile("cp.async.commit_group;\n");
    load_stage(1, GBK);
    asm volatile("cp.async.commit_group;\n");

    for (int kt = 0; kt < nk; kt++) {
        asm volatile("cp.async.wait_group 1;\n");
        __syncthreads();
        if (kt + 2 < nk) load_stage((kt + 2) % 3, (kt + 2) * GBK);
        asm volatile("cp.async.commit_group;\n");

        const float* Asc = sm + (kt % 3) * STG;
        const float* Bsc = Asc + A_STAGE;

#pragma unroll
        for (int kk = 0; kk < GBK; kk += 8) {
            uint32_t af[2][4], bf[8][2];
#pragma unroll
            for (int mi = 0; mi < 2; mi++) {
                const int r = wm + mi * 16 + g;
                af[mi][0] = __float_as_uint(Asc[r * ASTR + kk + t]);
                af[mi][1] = __float_as_uint(Asc[(r + 8) * ASTR + kk + t]);
                af[mi][2] = __float_as_uint(Asc[r * ASTR + kk + t + 4]);
                af[mi][3] = __float_as_uint(Asc[(r + 8) * ASTR + kk + t + 4]);
            }
#pragma unroll
            for (int ni = 0; ni < 8; ni++) {
                const int c = wn + ni * 8 + g;
                bf[ni][0] = __float_as_uint(Bsc[(kk + t) * BSTR + c]);
                bf[ni][1] = __float_as_uint(Bsc[(kk + t + 4) * BSTR + c]);
            }
#pragma unroll
            for (int mi = 0; mi < 2; mi++)
#pragma unroll
                for (int ni = 0; ni < 8; ni++) {
                    float* d = acc[mi][ni];
                    asm volatile(
                        "mma.sync.aligned.m16n8k8.row.col.f32.tf32.tf32.f32 "
                        "{%0,%1,%2,%3}, {%4,%5,%6,%7}, {%8,%9}, {%0,%1,%2,%3};\n"
                        : "+f"(d[0]), "+f"(d[1]), "+f"(d[2]), "+f"(d[3])
                        : "r"(af[mi][0]), "r"(af[mi][1]), "r"(af[mi][2]), "r"(af[mi][3]),
                          "r"(bf[ni][0]), "r"(bf[ni][1]));
                }
        }
    }

#pragma unroll
    for (int mi = 0; mi < 2; mi++) {
#pragma unroll
        for (int ni = 0; ni < 8; ni++) {
            const int row = bm + wm + mi * 16 + g;
            const int col = bn + wn + ni * 8 + (t << 1);
            float v0 = acc[mi][ni][0], v1 = acc[mi][ni][1];
            float v2 = acc[mi][ni][2], v3 = acc[mi][ni][3];
            if (BIAS) {
                const float b0 = bias[col], b1 = bias[col + 1];
                v0 += b0; v1 += b1; v2 += b0; v3 += b1;
            }
            if (RELU) {
                v0 = fmaxf(v0, 0.f); v1 = fmaxf(v1, 0.f);
                v2 = fmaxf(v2, 0.f); v3 = fmaxf(v3, 0.f);
            }
            if (ROUND) {
                v0 = roundtf(v0); v1 = roundtf(v1);
                v2 = roundtf(v2); v3 = roundtf(v3);
            }
            *(float2*)&C[(size_t)row * N + col]       = make_float2(v0, v1);
            *(float2*)&C[(size_t)(row + 8) * N + col] = make_float2(v2, v3);
        }
    }
}

// ---------------------------------------------------------------------------
// TF32 flash attention, pipelined.
// Grid (LL/128, B*H); 256 threads = 8 warps; warp w owns rows [w*16,w*16+16)
// x full 64-key tile. K-tile = 64, K/V double-buffered via cp.async; mask+pad
// tile staged through smem (latency hidden behind S-MMA).
// Inputs q/k/v pre-rounded tf32 -> raw fragment loads. P rounded at store.
// ---------------------------------------------------------------------------
#define KTT 64
#define NTT (LL / KTT)                 // 16
#define AQS 68                         // Q/K/P/M row stride (mod 32 = 4)
#define AVS 72                         // V row stride (mod 32 = 8)
#define Q_OFF  0
#define K_OFF  (128 * AQS)             // 8704
#define K_STG  (KTT * AQS)             // 4352
#define V_OFF  (K_OFF + 2 * K_STG)     // 17408
#define V_STG  (KTT * AVS)             // 4608
#define P_OFF  (V_OFF + 2 * V_STG)     // 26624
#define M_OFF  (P_OFF + 128 * AQS)     // 35328
#define PD_OFF (M_OFF + 128 * AQS)     // 44032
#define ATT_SMEM_BYTES ((PD_OFF + 64) * 4)   // 176,384 B

__global__ void __launch_bounds__(256) attn_tc_kernel(
    const float* __restrict__ Qb, const float* __restrict__ Kb,
    const float* __restrict__ Vb, const float* __restrict__ mask,
    const float* __restrict__ padf, float* __restrict__ ctx)
{
    extern __shared__ float smf[];

    const int b   = blockIdx.y >> 4;
    const int h   = blockIdx.y & 15;
    const int q0  = blockIdx.x * 128;
    const int tid = threadIdx.x;
    const int wid = tid >> 5;
    const int lane = tid & 31;
    const int g   = lane >> 2;
    const int t   = lane & 3;
    const int wm  = wid * 16;

    const uint32_t sbase = (uint32_t)__cvta_generic_to_shared(smf);

    // Q tile [128 x 64] + KV tile 0, one group
#pragma unroll
    for (int i = 0; i < 8; i++) {
        int id = tid + i * 256;
        int r = id >> 4, c = (id & 15) << 2;
        uint32_t dst = sbase + ((Q_OFF + r * AQS + c) << 2);
        const float* src = Qb + (size_t)(b * LL + q0 + r) * DD + h * HDIM + c;
        asm volatile("cp.async.cg.shared.global [%0], [%1], 16;\n" :: "r"(dst), "l"(src));
    }
#pragma unroll
    for (int i = 0; i < 4; i++) {
        int id = tid + i * 256;
        int r = id >> 4, c = (id & 15) << 2;
        size_t go = (size_t)(b * LL + r) * DD + h * HDIM + c;
        uint32_t dk = sbase + ((K_OFF + r * AQS + c) << 2);
        uint32_t dv = sbase + ((V_OFF + r * AVS + c) << 2);
        asm volatile("cp.async.cg.shared.global [%0], [%1], 16;\n" :: "r"(dk), "l"(Kb + go));
        asm volatile("cp.async.cg.shared.global [%0], [%1], 16;\n" :: "r"(dv), "l"(Vb + go));
    }
    asm volatile("cp.async.commit_group;\n");

    float o[8][4];
    float mrow[2] = {-1e30f, -1e30f}, lrow[2] = {0.f, 0.f};
#pragma unroll
    for (int ni = 0; ni < 8; ni++)
#pragma unroll
        for (int e = 0; e < 4; e++) o[ni][e] = 0.f;

    for (int kt = 0; kt < NTT; kt++) {
        const int k0 = kt * KTT;
        const int cur = kt & 1;
        const int nxt = cur ^ 1;

        asm volatile("cp.async.wait_group 0;\n");   // KV(kt) (+prev mask) done
        __syncthreads();

        // stage mask+pad tile kt (group B) — consumed after S-MMA
#pragma unroll
        for (int i = 0; i < 8; i++) {
            int id = tid + i * 256;
            int r = id >> 4, c = (id & 15) << 2;
            uint32_t dm = sbase + ((M_OFF + r * AQS + c) << 2);
            const float* srcm = mask + (size_t)(q0 + r) * LL + k0 + c;
            asm volatile("cp.async.cg.shared.global [%0], [%1], 16;\n" :: "r"(dm), "l"(srcm));
        }
        if (tid < 16) {
            uint32_t dp = sbase + ((PD_OFF + tid * 4) << 2);
            const float* srcp = padf + b * LL + k0 + tid * 4;
            asm volatile("cp.async.cg.shared.global [%0], [%1], 16;\n" :: "r"(dp), "l"(srcp));
        }
        asm volatile("cp.async.commit_group;\n");

        // prefetch KV(kt+1) (group C)
        if (kt + 1 < NTT) {
#pragma unroll
            for (int i = 0; i < 4; i++) {
                int id = tid + i * 256;
                int r = id >> 4, c = (id & 15) << 2;
                size_t go = (size_t)(b * LL + k0 + KTT + r) * DD + h * HDIM + c;
                uint32_t dk = sbase + ((K_OFF + nxt * K_STG + r * AQS + c) << 2);
                uint32_t dv = sbase + ((V_OFF + nxt * V_STG + r * AVS + c) << 2);
                asm volatile("cp.async.cg.shared.global [%0], [%1], 16;\n" :: "r"(dk), "l"(Kb + go));
                asm volatile("cp.async.cg.shared.global [%0], [%1], 16;\n" :: "r"(dv), "l"(Vb + go));
            }
        }
        asm volatile("cp.async.commit_group;\n");

        // ---- S[16 x 64] = Q @ K^T ----
        float s[8][4];
#pragma unroll
        for (int ni = 0; ni < 8; ni++)
#pragma unroll
            for (int e = 0; e < 4; e++) s[ni][e] = 0.f;

#pragma unroll
        for (int kk = 0; kk < HDIM; kk += 8) {
            uint32_t af[4], bf[8][2];
            af[0] = __float_as_uint(smf[Q_OFF + (wm + g) * AQS + kk + t]);
            af[1] = __float_as_uint(smf[Q_OFF + (wm + g + 8) * AQS + kk + t]);
            af[2] = __float_as_uint(smf[Q_OFF + (wm + g) * AQS + kk + t + 4]);
            af[3] = __float_as_uint(smf[Q_OFF + (wm + g + 8) * AQS + kk + t + 4]);
#pragma unroll
            for (int ni = 0; ni < 8; ni++) {
                const int key = ni * 8 + g;
                bf[ni][0] = __float_as_uint(smf[K_OFF + cur * K_STG + key * AQS + kk + t]);
                bf[ni][1] = __float_as_uint(smf[K_OFF + cur * K_STG + key * AQS + kk + t + 4]);
            }
#pragma unroll
            for (int ni = 0; ni < 8; ni++) {
                float* d = s[ni];
                asm volatile(
                    "mma.sync.aligned.m16n8k8.row.col.f32.tf32.tf32.f32 "
                    "{%0,%1,%2,%3}, {%4,%5,%6,%7}, {%8,%9}, {%0,%1,%2,%3};\n"
                    : "+f"(d[0]), "+f"(d[1]), "+f"(d[2]), "+f"(d[3])
                    : "r"(af[0]), "r"(af[1]), "r"(af[2]), "r"(af[3]),
                      "r"(bf[ni][0]), "r"(bf[ni][1]));
            }
        }

        // mask tile ready (only group C may remain pending)
        asm volatile("cp.async.wait_group 1;\n");
        __syncthreads();

        // ---- online softmax over 64 keys (warp-local rows) ----
#pragma unroll
        for (int hf = 0; hf < 2; hf++) {
            const int r = wm + g + hf * 8;
            float rm = -1e30f;
#pragma unroll
            for (int ni = 0; ni < 8; ni++) {
                const int kcl = ni * 8 + (t << 1);
                const float2 mk = *(const float2*)&smf[M_OFF + r * AQS + kcl];
                float v0 = s[ni][hf * 2 + 0] * 0.125f + mk.x + smf[PD_OFF + kcl];
                float v1 = s[ni][hf * 2 + 1] * 0.125f + mk.y + smf[PD_OFF + kcl + 1];
                s[ni][hf * 2 + 0] = v0;
                s[ni][hf * 2 + 1] = v1;
                rm = fmaxf(rm, fmaxf(v0, v1));
            }
            rm = fmaxf(rm, __shfl_xor_sync(0xffffffffu, rm, 1));
            rm = fmaxf(rm, __shfl_xor_sync(0xffffffffu, rm, 2));
            const float mnew = fmaxf(mrow[hf], rm);
            const float corr = __expf(mrow[hf] - mnew);
            mrow[hf] = mnew;
            float rs = 0.f;
#pragma unroll
            for (int ni = 0; ni < 8; ni++) {
                float p0 = __expf(s[ni][hf * 2 + 0] - mnew);
                float p1 = __expf(s[ni][hf * 2 + 1] - mnew);
                rs += p0 + p1;
                float2 st;
                st.x = roundtf(p0);
                st.y = roundtf(p1);
                *(float2*)&smf[P_OFF + r * AQS + ni * 8 + (t << 1)] = st;
            }
            rs += __shfl_xor_sync(0xffffffffu, rs, 1);
            rs += __shfl_xor_sync(0xffffffffu, rs, 2);
            lrow[hf] = lrow[hf] * corr + rs;
#pragma unroll
            for (int ni = 0; ni < 8; ni++) {
                o[ni][hf * 2 + 0] *= corr;
                o[ni][hf * 2 + 1] *= corr;
            }
        }
        __syncwarp();   // P rows are warp-private

        // ---- O[16 x 64] += P @ V ----
#pragma unroll
        for (int kk = 0; kk < KTT; kk += 8) {
            uint32_t ap[4], bv[8][2];
            ap[0] = __float_as_uint(smf[P_OFF + (wm + g) * AQS + kk + t]);
            ap[1] = __float_as_uint(smf[P_OFF + (wm + g + 8) * AQS + kk + t]);
            ap[2] = __float_as_uint(smf[P_OFF + (wm + g) * AQS + kk + t + 4]);
            ap[3] = __float_as_uint(smf[P_OFF + (wm + g + 8) * AQS + kk + t + 4]);
#pragma unroll
            for (int ni = 0; ni < 8; ni++) {
                const int c = ni * 8 + g;
                bv[ni][0] = __float_as_uint(smf[V_OFF + cur * V_STG + (kk + t) * AVS + c]);
                bv[ni][1] = __float_as_uint(smf[V_OFF + cur * V_STG + (kk + t + 4) * AVS + c]);
            }
#pragma unroll
            for (int ni = 0; ni < 8; ni++) {
                float* d = o[ni];
                asm volatile(
                    "mma.sync.aligned.m16n8k8.row.col.f32.tf32.tf32.f32 "
                    "{%0,%1,%2,%3}, {%4,%5,%6,%7}, {%8,%9}, {%0,%1,%2,%3};\n"
                    : "+f"(d[0]), "+f"(d[1]), "+f"(d[2]), "+f"(d[3])
                    : "r"(ap[0]), "r"(ap[1]), "r"(ap[2]), "r"(ap[3]),
                      "r"(bv[ni][0]), "r"(bv[ni][1]));
            }
        }
    }

    // ---- epilogue: normalize, round to tf32 (feeds Wo GEMM), store ----
    const float inv0 = 1.f / lrow[0];
    const float inv1 = 1.f / lrow[1];
#pragma unroll
    for (int ni = 0; ni < 8; ni++) {
        const int col = h * HDIM + ni * 8 + (t << 1);
        *(float2*)&ctx[(size_t)(b * LL + q0 + wm + g) * DD + col] =
            make_float2(roundtf(o[ni][0] * inv0), roundtf(o[ni][1] * inv0));
        *(float2*)&ctx[(size_t)(b * LL + q0 + wm + g + 8) * DD + col] =
            make_float2(roundtf(o[ni][2] * inv1), roundtf(o[ni][3] * inv1));
    }
}

// ---------------------------------------------------------------------------
// out = tf32_round(LayerNorm(x + r) * g + b)  (outputs always feed GEMMs)
// ---------------------------------------------------------------------------
__global__ void __launch_bounds__(256) ln_residual_kernel(
    const float* __restrict__ x, const float* __restrict__ r,
    const float* __restrict__ g, const float* __restrict__ be,
    float* __restrict__ out)
{
    __shared__ float red[8];
    const int row = blockIdx.x;
    const int t = threadIdx.x;

    const float4 a = ((const float4*)(x + (size_t)row * DD))[t];
    const float4 c = ((const float4*)(r + (size_t)row * DD))[t];
    float4 v = make_float4(a.x + c.x, a.y + c.y, a.z + c.z, a.w + c.w);

    float s = v.x + v.y + v.z + v.w;
#pragma unroll
    for (int o = 16; o >= 1; o >>= 1) s += __shfl_xor_sync(0xffffffffu, s, o);
    if ((t & 31) == 0) red[t >> 5] = s;
    __syncthreads();
    float tot = red[0] + red[1] + red[2] + red[3] + red[4] + red[5] + red[6] + red[7];
    const float mean = tot * (1.0f / DD);

    const float dx0 = v.x - mean, dx1 = v.y - mean, dx2 = v.z - mean, dx3 = v.w - mean;
    float sq = dx0 * dx0 + dx1 * dx1 + dx2 * dx2 + dx3 * dx3;
#pragma unroll
    for (int o = 16; o >= 1; o >>= 1) sq += __shfl_xor_sync(0xffffffffu, sq, o);
    __syncthreads();
    if ((t & 31) == 0) red[t >> 5] = sq;
    __syncthreads();
    float var = (red[0] + red[1] + red[2] + red[3] + red[4] + red[5] + red[6] + red[7]) * (1.0f / DD);
    const float rstd = rsqrtf(var + 1e-5f);

    const float4 gg = ((const float4*)g)[t];
    const float4 bb = ((const float4*)be)[t];
    float4 ov;
    ov.x = roundtf(dx0 * rstd * gg.x + bb.x);
    ov.y = roundtf(dx1 * rstd * gg.y + bb.y);
    ov.z = roundtf(dx2 * rstd * gg.z + bb.z);
    ov.w = roundtf(dx3 * rstd * gg.w + bb.w);
    ((float4*)(out + (size_t)row * DD))[t] = ov;
}

// ---------------------------------------------------------------------------
// Launch
// ---------------------------------------------------------------------------
extern "C" void kernel_launch(void* const* d_in, const int* in_sizes, int n_in,
                              void* d_out, int out_size)
{
    const float* T    = (const float*)d_in[0];
    const float* A    = (const float*)d_in[1];
    const float* mask = (const float*)d_in[2];
    const int*   pad  = (const int*)  d_in[3];
    const float* Wq   = (const float*)d_in[4];
    const float* bq   = (const float*)d_in[5];
    const float* Wk   = (const float*)d_in[6];
    const float* bk   = (const float*)d_in[7];
    const float* Wv   = (const float*)d_in[8];
    const float* bv   = (const float*)d_in[9];
    const float* Wo   = (const float*)d_in[10];
    const float* fW1  = (const float*)d_in[11];
    const float* fb1  = (const float*)d_in[12];
    const float* fW2  = (const float*)d_in[13];
    const float* fb2  = (const float*)d_in[14];
    const float* lng  = (const float*)d_in[15];
    const float* lnb  = (const float*)d_in[16];
    float* out = (float*)d_out;

    float *q, *k, *v, *ctx, *proj, *t1, *a1, *t2, *a2, *ffh;
    float *tr, *ar, *wq, *wk, *wv, *wo, *fw1, *fw2, *padf;
    cudaGetSymbolAddress((void**)&q,    g_q);
    cudaGetSymbolAddress((void**)&k,    g_k);
    cudaGetSymbolAddress((void**)&v,    g_v);
    cudaGetSymbolAddress((void**)&ctx,  g_ctx);
    cudaGetSymbolAddress((void**)&proj, g_proj);
    cudaGetSymbolAddress((void**)&t1,   g_t1);
    cudaGetSymbolAddress((void**)&a1,   g_a1);
    cudaGetSymbolAddress((void**)&t2,   g_t2);
    cudaGetSymbolAddress((void**)&a2,   g_a2);
    cudaGetSymbolAddress((void**)&ffh,  g_ffh);
    cudaGetSymbolAddress((void**)&tr,   g_tr);
    cudaGetSymbolAddress((void**)&ar,   g_ar);
    cudaGetSymbolAddress((void**)&wq,   g_wq);
    cudaGetSymbolAddress((void**)&wk,   g_wk);
    cudaGetSymbolAddress((void**)&wv,   g_wv);
    cudaGetSymbolAddress((void**)&wo,   g_wo);
    cudaGetSymbolAddress((void**)&fw1,  g_fw1);
    cudaGetSymbolAddress((void**)&fw2,  g_fw2);
    cudaGetSymbolAddress((void**)&padf, g_padf);

    cudaFuncSetAttribute(attn_tc_kernel,
                         cudaFuncAttributeMaxDynamicSharedMemorySize, ATT_SMEM_BYTES);
    cudaFuncSetAttribute(gemm_tf32<false, true,  true >,
                         cudaFuncAttributeMaxDynamicSharedMemorySize, GEMM_SMEM_BYTES);
    cudaFuncSetAttribute(gemm_tf32<false, false, false>,
                         cudaFuncAttributeMaxDynamicSharedMemorySize, GEMM_SMEM_BYTES);
    cudaFuncSetAttribute(gemm_tf32<true,  true,  true >,
                         cudaFuncAttributeMaxDynamicSharedMemorySize, GEMM_SMEM_BYTES);
    cudaFuncSetAttribute(gemm_tf32<false, true,  false>,
                         cudaFuncAttributeMaxDynamicSharedMemorySize, GEMM_SMEM_BYTES);

    // ---- pre-round weights + inputs to tf32 (once per replay) ----
    const int RB = 256;
    auto rc = [&](const float* src, float* dst, size_t nfloats) {
        int n4 = (int)(nfloats / 4);
        int grid = (n4 + RB * 4 - 1) / (RB * 4);
        round_copy_kernel<<<grid, RB>>>((const float4*)src, (float4*)dst, n4);
    };
    rc(T,   tr,  (size_t)MM * DD);
    rc(A,   ar,  (size_t)MM * DD);
    rc(Wq,  wq,  (size_t)4 * DD * DD);
    rc(Wk,  wk,  (size_t)4 * DD * DD);
    rc(Wv,  wv,  (size_t)4 * DD * DD);
    rc(Wo,  wo,  (size_t)4 * DD * DD);
    rc(fW1, fw1, (size_t)2 * DD * FFD);
    rc(fW2, fw2, (size_t)2 * FFD * DD);
    pad_to_float_kernel<<<(BB * LL + 255) / 256, 256>>>(pad, padf, BB * LL);

    dim3 thr(256);
    dim3 gP (DD  / GBN, MM / GBM);
    dim3 gF1(FFD / GBN, MM / GBM);
    dim3 gA (LL / 128, BB * HH);

    auto run_mha = [&](int i, const float* xq, const float* xkv,
                       const float* resid, float* dest) {
        gemm_tf32<false, true,  true ><<<gP, thr, GEMM_SMEM_BYTES>>>(xq,  wq + (size_t)i * DD * DD, bq + i * DD, q, MM, DD, DD);
        gemm_tf32<false, true,  true ><<<gP, thr, GEMM_SMEM_BYTES>>>(xkv, wk + (size_t)i * DD * DD, bk + i * DD, k, MM, DD, DD);
        gemm_tf32<false, true,  true ><<<gP, thr, GEMM_SMEM_BYTES>>>(xkv, wv + (size_t)i * DD * DD, bv + i * DD, v, MM, DD, DD);
        attn_tc_kernel<<<gA, thr, ATT_SMEM_BYTES>>>(q, k, v, mask, padf, ctx);
        gemm_tf32<false, false, false><<<gP, thr, GEMM_SMEM_BYTES>>>(ctx, wo + (size_t)i * DD * DD, nullptr, proj, MM, DD, DD);
        ln_residual_kernel<<<MM, thr>>>(resid, proj, lng + i * DD, lnb + i * DD, dest);
    };

    run_mha(0, tr, tr, T,  t1);
    run_mha(1, ar, ar, A,  a1);
    run_mha(2, t1, a1, t1, t2);
    run_mha(3, a1, t2, a1, a2);

    gemm_tf32<true,  true, true ><<<gF1, thr, GEMM_SMEM_BYTES>>>(t2, fw1, fb1, ffh, MM, FFD, DD);
    gemm_tf32<false, true, false><<<gP,  thr, GEMM_SMEM_BYTES>>>(ffh, fw2, fb2, out, MM, DD, FFD);
    gemm_tf32<true,  true, true ><<<gF1, thr, GEMM_SMEM_BYTES>>>(a2, fw1 + (size_t)DD * FFD, fb1 + FFD, ffh, MM, FFD, DD);
    gemm_tf32<false, true, false><<<gP,  thr, GEMM_SMEM_BYTES>>>(ffh, fw2 + (size_t)FFD * DD, fb2 + DD,
                                                                 out + (size_t)MM * DD, MM, DD, FFD);
}

// round 12
// speedup vs baseline: 4.0094x; 1.3462x over previous
#include <cuda_runtime.h>
#include <cuda_fp16.h>
#include <cstdint>
#include <math.h>

// Problem constants
#define BB   4
#define LL   1024
#define DD   1024
#define HH   16
#define HDIM 64
#define FFD  4096
#define MM   (BB * LL)   // 4096 rows

// ---------------------------------------------------------------------------
// Scratch (static __device__ arrays; no allocation allowed)
// ---------------------------------------------------------------------------
__device__ float  g_q   [MM * DD];          // fp32 tf32-rounded (attention in)
__device__ float  g_k   [MM * DD];
__device__ float  g_v   [MM * DD];
__device__ __half g_ctx [MM * DD];          // attention out -> Wo GEMM A
__device__ float  g_proj[MM * DD];          // Wo GEMM out -> LN
__device__ float  g_t1f [MM * DD];          // LN fp32 outs (residual path)
__device__ float  g_a1f [MM * DD];
__device__ float  g_t2f [MM * DD];
__device__ float  g_a2f [MM * DD];
__device__ __half g_t1h [MM * DD];          // LN fp16 outs (GEMM A path)
__device__ __half g_a1h [MM * DD];
__device__ __half g_t2h [MM * DD];
__device__ __half g_a2h [MM * DD];
__device__ __half g_ffh [MM * FFD];         // FFN hidden
__device__ __half g_tr  [MM * DD];          // fp16 copies of T, A
__device__ __half g_ar  [MM * DD];
// weights transposed to [N][K], fp16
__device__ __half g_wq  [4 * DD * DD];
__device__ __half g_wk  [4 * DD * DD];
__device__ __half g_wv  [4 * DD * DD];
__device__ __half g_wo  [4 * DD * DD];
__device__ __half g_fw1 [2 * DD * FFD];
__device__ __half g_fw2 [2 * FFD * DD];
__device__ float  g_padf[BB * LL];

__device__ __forceinline__ uint32_t f2tf32(float x) {
    uint32_t u;
    asm("cvt.rna.tf32.f32 %0, %1;" : "=r"(u) : "f"(x));
    return u;
}
__device__ __forceinline__ float roundtf(float x) {
    return __uint_as_float(f2tf32(x));
}

// ---------------------------------------------------------------------------
// Pre-pass kernels
// ---------------------------------------------------------------------------
__global__ void tohalf_kernel(const float4* __restrict__ in,
                              __half2* __restrict__ out, int n4)
{
    for (int i = blockIdx.x * blockDim.x + threadIdx.x; i < n4;
         i += gridDim.x * blockDim.x) {
        float4 v = in[i];
        out[2 * i]     = __floats2half2_rn(v.x, v.y);
        out[2 * i + 1] = __floats2half2_rn(v.z, v.w);
    }
}

// dst[N][K] (half) = src[K][N] (float)
__global__ void __launch_bounds__(256) transpose_half_kernel(
    const float* __restrict__ src, __half* __restrict__ dst, int K, int N)
{
    __shared__ float tile[32][33];
    const int n0 = blockIdx.x * 32, k0 = blockIdx.y * 32;
    const int tx = threadIdx.x, ty = threadIdx.y;   // 32 x 8
#pragma unroll
    for (int j = 0; j < 4; j++)
        tile[ty + j * 8][tx] = src[(size_t)(k0 + ty + j * 8) * N + n0 + tx];
    __syncthreads();
#pragma unroll
    for (int j = 0; j < 4; j++)
        dst[(size_t)(n0 + ty + j * 8) * K + k0 + tx] = __float2half_rn(tile[tx][ty + j * 8]);
}

__global__ void pad_to_float_kernel(const int* __restrict__ pad,
                                    float* __restrict__ padf, int n)
{
    int i = blockIdx.x * blockDim.x + threadIdx.x;
    if (i < n) padf[i] = (float)pad[i];
}

// ---------------------------------------------------------------------------
// FP16 tensor-core GEMM: C[M,N] = A[M,K] @ BT[N,K]^T (+bias)(+relu).
// A, BT fp16; accumulate fp32. 128x128 CTA tile, BK=32, m16n8k16,
// 3-stage cp.async, 8 warps (4x2, 32x64 per warp), 2 CTAs/SM.
// OUTMODE: 0 = float, 1 = float tf32-rounded, 2 = half.
// ---------------------------------------------------------------------------
#define GBK 32
#define HRS 40                           // smem row stride in halves (80 B)
#define HOP_STAGE (128 * HRS)            // halves per operand per stage (5120)
#define HSTG (2 * HOP_STAGE)             // halves per stage (A+B)
#define GEMM_SMEM_BYTES (3 * HSTG * 2)   // 61,440 B

template <bool RELU, bool BIAS, int OUTMODE>
__global__ void __launch_bounds__(256, 2) gemm_f16(
    const __half* __restrict__ A, const __half* __restrict__ BT,
    const float* __restrict__ bias, void* __restrict__ Cv,
    int M, int N, int K)
{
    extern __shared__ __half smh[];

    const int tid  = threadIdx.x;
    const int bm   = blockIdx.y * 128;
    const int bn   = blockIdx.x * 128;
    const int wid  = tid >> 5;
    const int lane = tid & 31;
    const int g    = lane >> 2;
    const int t    = lane & 3;
    const int wm   = (wid & 3) * 32;
    const int wn   = (wid >> 2) * 64;

    const uint32_t sbase = (uint32_t)__cvta_generic_to_shared(smh);
    const int nk = K / GBK;

    // one stage: A[128 rows x 32 halves] + B[128 rows x 32 halves]
    auto load_stage = [&](int slot, int k0) {
#pragma unroll
        for (int i = 0; i < 2; i++) {
            int id = tid + i * 256;              // 0..511
            int r  = id >> 2;                    // 0..127
            int cb = (id & 3) << 4;              // byte col 0,16,32,48
            uint32_t dstA = sbase + (uint32_t)(slot * HSTG * 2 + r * (HRS * 2) + cb);
            uint32_t dstB = dstA + HOP_STAGE * 2;
            const __half* srcA = A  + (size_t)(bm + r) * K + k0 + (cb >> 1);
            const __half* srcB = BT + (size_t)(bn + r) * K + k0 + (cb >> 1);
            asm volatile("cp.async.cg.shared.global [%0], [%1], 16;\n"
                         :: "r"(dstA), "l"(srcA));
            asm volatile("cp.async.cg.shared.global [%0], [%1], 16;\n"
                         :: "r"(dstB), "l"(srcB));
        }
    };

    float acc[2][8][4];
#pragma unroll
    for (int mi = 0; mi < 2; mi++)
#pragma unroll
        for (int ni = 0; ni < 8; ni++)
#pragma unroll
            for (int e = 0; e < 4; e++) acc[mi][ni][e] = 0.f;

    load_stage(0, 0);
    asm volatile("cp.async.commit_group;\n");
    load_stage(1, GBK);
    asm volatile("cp.async.commit_group;\n");

    for (int kt = 0; kt < nk; kt++) {
        asm volatile("cp.async.wait_group 1;\n");
        __syncthreads();
        if (kt + 2 < nk) load_stage((kt + 2) % 3, (kt + 2) * GBK);
        asm volatile("cp.async.commit_group;\n");

        const __half* Asc = smh + (kt % 3) * HSTG;
        const __half* Bsc = Asc + HOP_STAGE;

#pragma unroll
        for (int kk = 0; kk < GBK; kk += 16) {
            uint32_t af[2][4], bf[8][2];
#pragma unroll
            for (int mi = 0; mi < 2; mi++) {
                const int r = wm + mi * 16 + g;
                af[mi][0] = *(const uint32_t*)&Asc[r * HRS + kk + 2 * t];
                af[mi][1] = *(const uint32_t*)&Asc[(r + 8) * HRS + kk + 2 * t];
                af[mi][2] = *(const uint32_t*)&Asc[r * HRS + kk + 2 * t + 8];
                af[mi][3] = *(const uint32_t*)&Asc[(r + 8) * HRS + kk + 2 * t + 8];
            }
#pragma unroll
            for (int ni = 0; ni < 8; ni++) {
                const int c = wn + ni * 8 + g;
                bf[ni][0] = *(const uint32_t*)&Bsc[c * HRS + kk + 2 * t];
                bf[ni][1] = *(const uint32_t*)&Bsc[c * HRS + kk + 2 * t + 8];
            }
#pragma unroll
            for (int mi = 0; mi < 2; mi++)
#pragma unroll
                for (int ni = 0; ni < 8; ni++) {
                    float* d = acc[mi][ni];
                    asm volatile(
                        "mma.sync.aligned.m16n8k16.row.col.f32.f16.f16.f32 "
                        "{%0,%1,%2,%3}, {%4,%5,%6,%7}, {%8,%9}, {%0,%1,%2,%3};\n"
                        : "+f"(d[0]), "+f"(d[1]), "+f"(d[2]), "+f"(d[3])
                        : "r"(af[mi][0]), "r"(af[mi][1]), "r"(af[mi][2]), "r"(af[mi][3]),
                          "r"(bf[ni][0]), "r"(bf[ni][1]));
                }
        }
    }

#pragma unroll
    for (int mi = 0; mi < 2; mi++) {
#pragma unroll
        for (int ni = 0; ni < 8; ni++) {
            const int row = bm + wm + mi * 16 + g;
            const int col = bn + wn + ni * 8 + (t << 1);
            float v0 = acc[mi][ni][0], v1 = acc[mi][ni][1];
            float v2 = acc[mi][ni][2], v3 = acc[mi][ni][3];
            if (BIAS) {
                const float b0 = bias[col], b1 = bias[col + 1];
                v0 += b0; v1 += b1; v2 += b0; v3 += b1;
            }
            if (RELU) {
                v0 = fmaxf(v0, 0.f); v1 = fmaxf(v1, 0.f);
                v2 = fmaxf(v2, 0.f); v3 = fmaxf(v3, 0.f);
            }
            if (OUTMODE == 2) {
                __half* Ch = (__half*)Cv;
                *(__half2*)&Ch[(size_t)row * N + col]       = __floats2half2_rn(v0, v1);
                *(__half2*)&Ch[(size_t)(row + 8) * N + col] = __floats2half2_rn(v2, v3);
            } else {
                if (OUTMODE == 1) {
                    v0 = roundtf(v0); v1 = roundtf(v1);
                    v2 = roundtf(v2); v3 = roundtf(v3);
                }
                float* Cf = (float*)Cv;
                *(float2*)&Cf[(size_t)row * N + col]       = make_float2(v0, v1);
                *(float2*)&Cf[(size_t)(row + 8) * N + col] = make_float2(v2, v3);
            }
        }
    }
}

// ---------------------------------------------------------------------------
// TF32 flash attention (identical to round-10 passing version except the
// epilogue stores ctx as fp16 for the Wo GEMM).
// ---------------------------------------------------------------------------
#define KTT 64
#define NTT (LL / KTT)
#define AQS 68
#define AVS 72
#define Q_OFF  0
#define K_OFF  (128 * AQS)
#define K_STG  (KTT * AQS)
#define V_OFF  (K_OFF + 2 * K_STG)
#define V_STG  (KTT * AVS)
#define P_OFF  (V_OFF + 2 * V_STG)
#define M_OFF  (P_OFF + 128 * AQS)
#define PD_OFF (M_OFF + 128 * AQS)
#define ATT_SMEM_BYTES ((PD_OFF + 64) * 4)

__global__ void __launch_bounds__(256) attn_tc_kernel(
    const float* __restrict__ Qb, const float* __restrict__ Kb,
    const float* __restrict__ Vb, const float* __restrict__ mask,
    const float* __restrict__ padf, __half* __restrict__ ctx)
{
    extern __shared__ float smf[];

    const int b   = blockIdx.y >> 4;
    const int h   = blockIdx.y & 15;
    const int q0  = blockIdx.x * 128;
    const int tid = threadIdx.x;
    const int wid = tid >> 5;
    const int lane = tid & 31;
    const int g   = lane >> 2;
    const int t   = lane & 3;
    const int wm  = wid * 16;

    const uint32_t sbase = (uint32_t)__cvta_generic_to_shared(smf);

#pragma unroll
    for (int i = 0; i < 8; i++) {
        int id = tid + i * 256;
        int r = id >> 4, c = (id & 15) << 2;
        uint32_t dst = sbase + ((Q_OFF + r * AQS + c) << 2);
        const float* src = Qb + (size_t)(b * LL + q0 + r) * DD + h * HDIM + c;
        asm volatile("cp.async.cg.shared.global [%0], [%1], 16;\n" :: "r"(dst), "l"(src));
    }
#pragma unroll
    for (int i = 0; i < 4; i++) {
        int id = tid + i * 256;
        int r = id >> 4, c = (id & 15) << 2;
        size_t go = (size_t)(b * LL + r) * DD + h * HDIM + c;
        uint32_t dk = sbase + ((K_OFF + r * AQS + c) << 2);
        uint32_t dv = sbase + ((V_OFF + r * AVS + c) << 2);
        asm volatile("cp.async.cg.shared.global [%0], [%1], 16;\n" :: "r"(dk), "l"(Kb + go));
        asm volatile("cp.async.cg.shared.global [%0], [%1], 16;\n" :: "r"(dv), "l"(Vb + go));
    }
    asm volatile("cp.async.commit_group;\n");

    float o[8][4];
    float mrow[2] = {-1e30f, -1e30f}, lrow[2] = {0.f, 0.f};
#pragma unroll
    for (int ni = 0; ni < 8; ni++)
#pragma unroll
        for (int e = 0; e < 4; e++) o[ni][e] = 0.f;

    for (int kt = 0; kt < NTT; kt++) {
        const int k0 = kt * KTT;
        const int cur = kt & 1;
        const int nxt = cur ^ 1;

        asm volatile("cp.async.wait_group 0;\n");
        __syncthreads();

#pragma unroll
        for (int i = 0; i < 8; i++) {
            int id = tid + i * 256;
            int r = id >> 4, c = (id & 15) << 2;
            uint32_t dm = sbase + ((M_OFF + r * AQS + c) << 2);
            const float* srcm = mask + (size_t)(q0 + r) * LL + k0 + c;
            asm volatile("cp.async.cg.shared.global [%0], [%1], 16;\n" :: "r"(dm), "l"(srcm));
        }
        if (tid < 16) {
            uint32_t dp = sbase + ((PD_OFF + tid * 4) << 2);
            const float* srcp = padf + b * LL + k0 + tid * 4;
            asm volatile("cp.async.cg.shared.global [%0], [%1], 16;\n" :: "r"(dp), "l"(srcp));
        }
        asm volatile("cp.async.commit_group;\n");

        if (kt + 1 < NTT) {
#pragma unroll
            for (int i = 0; i < 4; i++) {
                int id = tid + i * 256;
                int r = id >> 4, c = (id & 15) << 2;
                size_t go = (size_t)(b * LL + k0 + KTT + r) * DD + h * HDIM + c;
                uint32_t dk = sbase + ((K_OFF + nxt * K_STG + r * AQS + c) << 2);
                uint32_t dv = sbase + ((V_OFF + nxt * V_STG + r * AVS + c) << 2);
                asm volatile("cp.async.cg.shared.global [%0], [%1], 16;\n" :: "r"(dk), "l"(Kb + go));
                asm volatile("cp.async.cg.shared.global [%0], [%1], 16;\n" :: "r"(dv), "l"(Vb + go));
            }
        }
        asm volatile("cp.async.commit_group;\n");

        float s[8][4];
#pragma unroll
        for (int ni = 0; ni < 8; ni++)
#pragma unroll
            for (int e = 0; e < 4; e++) s[ni][e] = 0.f;

#pragma unroll
        for (int kk = 0; kk < HDIM; kk += 8) {
            uint32_t af[4], bf[8][2];
            af[0] = __float_as_uint(smf[Q_OFF + (wm + g) * AQS + kk + t]);
            af[1] = __float_as_uint(smf[Q_OFF + (wm + g + 8) * AQS + kk + t]);
            af[2] = __float_as_uint(smf[Q_OFF + (wm + g) * AQS + kk + t + 4]);
            af[3] = __float_as_uint(smf[Q_OFF + (wm + g + 8) * AQS + kk + t + 4]);
#pragma unroll
            for (int ni = 0; ni < 8; ni++) {
                const int key = ni * 8 + g;
                bf[ni][0] = __float_as_uint(smf[K_OFF + cur * K_STG + key * AQS + kk + t]);
                bf[ni][1] = __float_as_uint(smf[K_OFF + cur * K_STG + key * AQS + kk + t + 4]);
            }
#pragma unroll
            for (int ni = 0; ni < 8; ni++) {
                float* d = s[ni];
                asm volatile(
                    "mma.sync.aligned.m16n8k8.row.col.f32.tf32.tf32.f32 "
                    "{%0,%1,%2,%3}, {%4,%5,%6,%7}, {%8,%9}, {%0,%1,%2,%3};\n"
                    : "+f"(d[0]), "+f"(d[1]), "+f"(d[2]), "+f"(d[3])
                    : "r"(af[0]), "r"(af[1]), "r"(af[2]), "r"(af[3]),
                      "r"(bf[ni][0]), "r"(bf[ni][1]));
            }
        }

        asm volatile("cp.async.wait_group 1;\n");
        __syncthreads();

#pragma unroll
        for (int hf = 0; hf < 2; hf++) {
            const int r = wm + g + hf * 8;
            float rm = -1e30f;
#pragma unroll
            for (int ni = 0; ni < 8; ni++) {
                const int kcl = ni * 8 + (t << 1);
                const float2 mk = *(const float2*)&smf[M_OFF + r * AQS + kcl];
                float v0 = s[ni][hf * 2 + 0] * 0.125f + mk.x + smf[PD_OFF + kcl];
                float v1 = s[ni][hf * 2 + 1] * 0.125f + mk.y + smf[PD_OFF + kcl + 1];
                s[ni][hf * 2 + 0] = v0;
                s[ni][hf * 2 + 1] = v1;
                rm = fmaxf(rm, fmaxf(v0, v1));
            }
            rm = fmaxf(rm, __shfl_xor_sync(0xffffffffu, rm, 1));
            rm = fmaxf(rm, __shfl_xor_sync(0xffffffffu, rm, 2));
            const float mnew = fmaxf(mrow[hf], rm);
            const float corr = __expf(mrow[hf] - mnew);
            mrow[hf] = mnew;
            float rs = 0.f;
#pragma unroll
            for (int ni = 0; ni < 8; ni++) {
                float p0 = __expf(s[ni][hf * 2 + 0] - mnew);
                float p1 = __expf(s[ni][hf * 2 + 1] - mnew);
                rs += p0 + p1;
                float2 st;
                st.x = roundtf(p0);
                st.y = roundtf(p1);
                *(float2*)&smf[P_OFF + r * AQS + ni * 8 + (t << 1)] = st;
            }
            rs += __shfl_xor_sync(0xffffffffu, rs, 1);
            rs += __shfl_xor_sync(0xffffffffu, rs, 2);
            lrow[hf] = lrow[hf] * corr + rs;
#pragma unroll
            for (int ni = 0; ni < 8; ni++) {
                o[ni][hf * 2 + 0] *= corr;
                o[ni][hf * 2 + 1] *= corr;
            }
        }
        __syncwarp();

#pragma unroll
        for (int kk = 0; kk < KTT; kk += 8) {
            uint32_t ap[4], bv[8][2];
            ap[0] = __float_as_uint(smf[P_OFF + (wm + g) * AQS + kk + t]);
            ap[1] = __float_as_uint(smf[P_OFF + (wm + g + 8) * AQS + kk + t]);
            ap[2] = __float_as_uint(smf[P_OFF + (wm + g) * AQS + kk + t + 4]);
            ap[3] = __float_as_uint(smf[P_OFF + (wm + g + 8) * AQS + kk + t + 4]);
#pragma unroll
            for (int ni = 0; ni < 8; ni++) {
                const int c = ni * 8 + g;
                bv[ni][0] = __float_as_uint(smf[V_OFF + cur * V_STG + (kk + t) * AVS + c]);
                bv[ni][1] = __float_as_uint(smf[V_OFF + cur * V_STG + (kk + t + 4) * AVS + c]);
            }
#pragma unroll
            for (int ni = 0; ni < 8; ni++) {
                float* d = o[ni];
                asm volatile(
                    "mma.sync.aligned.m16n8k8.row.col.f32.tf32.tf32.f32 "
                    "{%0,%1,%2,%3}, {%4,%5,%6,%7}, {%8,%9}, {%0,%1,%2,%3};\n"
                    : "+f"(d[0]), "+f"(d[1]), "+f"(d[2]), "+f"(d[3])
                    : "r"(ap[0]), "r"(ap[1]), "r"(ap[2]), "r"(ap[3]),
                      "r"(bv[ni][0]), "r"(bv[ni][1]));
            }
        }
    }

    const float inv0 = 1.f / lrow[0];
    const float inv1 = 1.f / lrow[1];
#pragma unroll
    for (int ni = 0; ni < 8; ni++) {
        const int col = h * HDIM + ni * 8 + (t << 1);
        *(__half2*)&ctx[(size_t)(b * LL + q0 + wm + g) * DD + col] =
            __floats2half2_rn(o[ni][0] * inv0, o[ni][1] * inv0);
        *(__half2*)&ctx[(size_t)(b * LL + q0 + wm + g + 8) * DD + col] =
            __floats2half2_rn(o[ni][2] * inv1, o[ni][3] * inv1);
    }
}

// ---------------------------------------------------------------------------
// LayerNorm(x + r) * g + b -> dual output: fp32 (residual) + fp16 (GEMM A)
// ---------------------------------------------------------------------------
__global__ void __launch_bounds__(256) ln_residual_kernel(
    const float* __restrict__ x, const float* __restrict__ r,
    const float* __restrict__ g, const float* __restrict__ be,
    float* __restrict__ outf, __half* __restrict__ outh)
{
    __shared__ float red[8];
    const int row = blockIdx.x;
    const int t = threadIdx.x;

    const float4 a = ((const float4*)(x + (size_t)row * DD))[t];
    const float4 c = ((const float4*)(r + (size_t)row * DD))[t];
    float4 v = make_float4(a.x + c.x, a.y + c.y, a.z + c.z, a.w + c.w);

    float s = v.x + v.y + v.z + v.w;
#pragma unroll
    for (int o = 16; o >= 1; o >>= 1) s += __shfl_xor_sync(0xffffffffu, s, o);
    if ((t & 31) == 0) red[t >> 5] = s;
    __syncthreads();
    float tot = red[0] + red[1] + red[2] + red[3] + red[4] + red[5] + red[6] + red[7];
    const float mean = tot * (1.0f / DD);

    const float dx0 = v.x - mean, dx1 = v.y - mean, dx2 = v.z - mean, dx3 = v.w - mean;
    float sq = dx0 * dx0 + dx1 * dx1 + dx2 * dx2 + dx3 * dx3;
#pragma unroll
    for (int o = 16; o >= 1; o >>= 1) sq += __shfl_xor_sync(0xffffffffu, sq, o);
    __syncthreads();
    if ((t & 31) == 0) red[t >> 5] = sq;
    __syncthreads();
    float var = (red[0] + red[1] + red[2] + red[3] + red[4] + red[5] + red[6] + red[7]) * (1.0f / DD);
    const float rstd = rsqrtf(var + 1e-5f);

    const float4 gg = ((const float4*)g)[t];
    const float4 bb = ((const float4*)be)[t];
    float4 ov;
    ov.x = dx0 * rstd * gg.x + bb.x;
    ov.y = dx1 * rstd * gg.y + bb.y;
    ov.z = dx2 * rstd * gg.z + bb.z;
    ov.w = dx3 * rstd * gg.w + bb.w;
    ((float4*)(outf + (size_t)row * DD))[t] = ov;
    __half2* oh = (__half2*)(outh + (size_t)row * DD) + 2 * t;
    oh[0] = __floats2half2_rn(ov.x, ov.y);
    oh[1] = __floats2half2_rn(ov.z, ov.w);
}

// ---------------------------------------------------------------------------
// Launch
// ---------------------------------------------------------------------------
extern "C" void kernel_launch(void* const* d_in, const int* in_sizes, int n_in,
                              void* d_out, int out_size)
{
    const float* T    = (const float*)d_in[0];
    const float* A    = (const float*)d_in[1];
    const float* mask = (const float*)d_in[2];
    const int*   pad  = (const int*)  d_in[3];
    const float* Wq   = (const float*)d_in[4];
    const float* bq   = (const float*)d_in[5];
    const float* Wk   = (const float*)d_in[6];
    const float* bk   = (const float*)d_in[7];
    const float* Wv   = (const float*)d_in[8];
    const float* bv   = (const float*)d_in[9];
    const float* Wo   = (const float*)d_in[10];
    const float* fW1  = (const float*)d_in[11];
    const float* fb1  = (const float*)d_in[12];
    const float* fW2  = (const float*)d_in[13];
    const float* fb2  = (const float*)d_in[14];
    const float* lng  = (const float*)d_in[15];
    const float* lnb  = (const float*)d_in[16];
    float* out = (float*)d_out;

    float *q, *k, *v, *proj, *t1f, *a1f, *t2f, *a2f, *padf;
    __half *ctx, *t1h, *a1h, *t2h, *a2h, *ffh, *tr, *ar;
    __half *wq, *wk, *wv, *wo, *fw1, *fw2;
    cudaGetSymbolAddress((void**)&q,    g_q);
    cudaGetSymbolAddress((void**)&k,    g_k);
    cudaGetSymbolAddress((void**)&v,    g_v);
    cudaGetSymbolAddress((void**)&ctx,  g_ctx);
    cudaGetSymbolAddress((void**)&proj, g_proj);
    cudaGetSymbolAddress((void**)&t1f,  g_t1f);
    cudaGetSymbolAddress((void**)&a1f,  g_a1f);
    cudaGetSymbolAddress((void**)&t2f,  g_t2f);
    cudaGetSymbolAddress((void**)&a2f,  g_a2f);
    cudaGetSymbolAddress((void**)&t1h,  g_t1h);
    cudaGetSymbolAddress((void**)&a1h,  g_a1h);
    cudaGetSymbolAddress((void**)&t2h,  g_t2h);
    cudaGetSymbolAddress((void**)&a2h,  g_a2h);
    cudaGetSymbolAddress((void**)&ffh,  g_ffh);
    cudaGetSymbolAddress((void**)&tr,   g_tr);
    cudaGetSymbolAddress((void**)&ar,   g_ar);
    cudaGetSymbolAddress((void**)&wq,   g_wq);
    cudaGetSymbolAddress((void**)&wk,   g_wk);
    cudaGetSymbolAddress((void**)&wv,   g_wv);
    cudaGetSymbolAddress((void**)&wo,   g_wo);
    cudaGetSymbolAddress((void**)&fw1,  g_fw1);
    cudaGetSymbolAddress((void**)&fw2,  g_fw2);
    cudaGetSymbolAddress((void**)&padf, g_padf);

    cudaFuncSetAttribute(attn_tc_kernel,
                         cudaFuncAttributeMaxDynamicSharedMemorySize, ATT_SMEM_BYTES);
    cudaFuncSetAttribute(gemm_f16<false, true,  1>,
                         cudaFuncAttributeMaxDynamicSharedMemorySize, GEMM_SMEM_BYTES);
    cudaFuncSetAttribute(gemm_f16<false, false, 0>,
                         cudaFuncAttributeMaxDynamicSharedMemorySize, GEMM_SMEM_BYTES);
    cudaFuncSetAttribute(gemm_f16<true,  true,  2>,
                         cudaFuncAttributeMaxDynamicSharedMemorySize, GEMM_SMEM_BYTES);
    cudaFuncSetAttribute(gemm_f16<false, true,  0>,
                         cudaFuncAttributeMaxDynamicSharedMemorySize, GEMM_SMEM_BYTES);

    // ---- pre-pass: inputs -> fp16; weights -> transposed fp16 ----
    const int RB = 256;
    auto th = [&](const float* src, __half* dst, size_t nfloats) {
        int n4 = (int)(nfloats / 4);
        int grid = (n4 + RB * 4 - 1) / (RB * 4);
        tohalf_kernel<<<grid, RB>>>((const float4*)src, (__half2*)dst, n4);
    };
    th(T, tr, (size_t)MM * DD);
    th(A, ar, (size_t)MM * DD);
    dim3 tb(32, 8);
    auto tp = [&](const float* src, __half* dst, int K, int N) {
        transpose_half_kernel<<<dim3(N / 32, K / 32), tb>>>(src, dst, K, N);
    };
    for (int i = 0; i < 4; i++) {
        tp(Wq + (size_t)i * DD * DD, wq + (size_t)i * DD * DD, DD, DD);
        tp(Wk + (size_t)i * DD * DD, wk + (size_t)i * DD * DD, DD, DD);
        tp(Wv + (size_t)i * DD * DD, wv + (size_t)i * DD * DD, DD, DD);
        tp(Wo + (size_t)i * DD * DD, wo + (size_t)i * DD * DD, DD, DD);
    }
    for (int i = 0; i < 2; i++) {
        tp(fW1 + (size_t)i * DD * FFD, fw1 + (size_t)i * FFD * DD, DD, FFD);
        tp(fW2 + (size_t)i * FFD * DD, fw2 + (size_t)i * DD * FFD, FFD, DD);
    }
    pad_to_float_kernel<<<(BB * LL + 255) / 256, 256>>>(pad, padf, BB * LL);

    dim3 thr(256);
    dim3 gP (DD  / 128, MM / 128);
    dim3 gF1(FFD / 128, MM / 128);
    dim3 gA (LL / 128, BB * HH);

    auto run_mha = [&](int i, const __half* xq, const __half* xkv,
                       const float* resid, float* destf, __half* desth) {
        gemm_f16<false, true,  1><<<gP, thr, GEMM_SMEM_BYTES>>>(xq,  wq + (size_t)i * DD * DD, bq + i * DD, q, MM, DD, DD);
        gemm_f16<false, true,  1><<<gP, thr, GEMM_SMEM_BYTES>>>(xkv, wk + (size_t)i * DD * DD, bk + i * DD, k, MM, DD, DD);
        gemm_f16<false, true,  1><<<gP, thr, GEMM_SMEM_BYTES>>>(xkv, wv + (size_t)i * DD * DD, bv + i * DD, v, MM, DD, DD);
        attn_tc_kernel<<<gA, thr, ATT_SMEM_BYTES>>>(q, k, v, mask, padf, ctx);
        gemm_f16<false, false, 0><<<gP, thr, GEMM_SMEM_BYTES>>>(ctx, wo + (size_t)i * DD * DD, nullptr, proj, MM, DD, DD);
        ln_residual_kernel<<<MM, thr>>>(resid, proj, lng + i * DD, lnb + i * DD, destf, desth);
    };

    run_mha(0, tr,  tr,  T,   t1f, t1h);
    run_mha(1, ar,  ar,  A,   a1f, a1h);
    run_mha(2, t1h, a1h, t1f, t2f, t2h);
    run_mha(3, a1h, t2h, a1f, a2f, a2h);

    gemm_f16<true,  true, 2><<<gF1, thr, GEMM_SMEM_BYTES>>>(t2h, fw1, fb1, ffh, MM, FFD, DD);
    gemm_f16<false, true, 0><<<gP,  thr, GEMM_SMEM_BYTES>>>(ffh, fw2, fb2, out, MM, DD, FFD);
    gemm_f16<true,  true, 2><<<gF1, thr, GEMM_SMEM_BYTES>>>(a2h, fw1 + (size_t)FFD * DD, fb1 + FFD, ffh, MM, FFD, DD);
    gemm_f16<false, true, 0><<<gP,  thr, GEMM_SMEM_BYTES>>>(ffh, fw2 + (size_t)DD * FFD, fb2 + DD,
                                                            out + (size_t)MM * DD, MM, DD, FFD);
}

// round 13
// speedup vs baseline: 4.6028x; 1.1480x over previous
#include <cuda_runtime.h>
#include <cuda_fp16.h>
#include <cstdint>
#include <math.h>

// Problem constants
#define BB   4
#define LL   1024
#define DD   1024
#define HH   16
#define HDIM 64
#define FFD  4096
#define MM   (BB * LL)   // 4096 rows

// ---------------------------------------------------------------------------
// Scratch (static __device__ arrays; no allocation allowed)
// ---------------------------------------------------------------------------
__device__ __half g_q   [MM * DD];          // fp16 Q/K/V (attention in)
__device__ __half g_k   [MM * DD];
__device__ __half g_v   [MM * DD];
__device__ __half g_ctx [MM * DD];          // attention out -> Wo GEMM A
__device__ float  g_proj[MM * DD];          // Wo GEMM out -> LN
__device__ float  g_t1f [MM * DD];          // LN fp32 outs (residual path)
__device__ float  g_a1f [MM * DD];
__device__ float  g_t2f [MM * DD];
__device__ float  g_a2f [MM * DD];
__device__ __half g_t1h [MM * DD];          // LN fp16 outs (GEMM A path)
__device__ __half g_a1h [MM * DD];
__device__ __half g_t2h [MM * DD];
__device__ __half g_a2h [MM * DD];
__device__ __half g_ffh [MM * FFD];         // FFN hidden
__device__ __half g_tr  [MM * DD];          // fp16 copies of T, A
__device__ __half g_ar  [MM * DD];
// weights transposed to [N][K], fp16
__device__ __half g_wq  [4 * DD * DD];
__device__ __half g_wk  [4 * DD * DD];
__device__ __half g_wv  [4 * DD * DD];
__device__ __half g_wo  [4 * DD * DD];
__device__ __half g_fw1 [2 * DD * FFD];
__device__ __half g_fw2 [2 * FFD * DD];
__device__ float  g_padf[BB * LL];

// ---------------------------------------------------------------------------
// Pre-pass kernels
// ---------------------------------------------------------------------------
__global__ void tohalf_kernel(const float4* __restrict__ in,
                              __half2* __restrict__ out, int n4)
{
    for (int i = blockIdx.x * blockDim.x + threadIdx.x; i < n4;
         i += gridDim.x * blockDim.x) {
        float4 v = in[i];
        out[2 * i]     = __floats2half2_rn(v.x, v.y);
        out[2 * i + 1] = __floats2half2_rn(v.z, v.w);
    }
}

// dst[N][K] (half) = src[K][N] (float)
__global__ void __launch_bounds__(256) transpose_half_kernel(
    const float* __restrict__ src, __half* __restrict__ dst, int K, int N)
{
    __shared__ float tile[32][33];
    const int n0 = blockIdx.x * 32, k0 = blockIdx.y * 32;
    const int tx = threadIdx.x, ty = threadIdx.y;   // 32 x 8
#pragma unroll
    for (int j = 0; j < 4; j++)
        tile[ty + j * 8][tx] = src[(size_t)(k0 + ty + j * 8) * N + n0 + tx];
    __syncthreads();
#pragma unroll
    for (int j = 0; j < 4; j++)
        dst[(size_t)(n0 + ty + j * 8) * K + k0 + tx] = __float2half_rn(tile[tx][ty + j * 8]);
}

__global__ void pad_to_float_kernel(const int* __restrict__ pad,
                                    float* __restrict__ padf, int n)
{
    int i = blockIdx.x * blockDim.x + threadIdx.x;
    if (i < n) padf[i] = (float)pad[i];
}

// ---------------------------------------------------------------------------
// FP16 tensor-core GEMM (unchanged from round 12 — known good).
// OUTMODE: 0 = float, 2 = half.
// ---------------------------------------------------------------------------
#define GBK 32
#define HRS 40                           // smem row stride in halves (80 B)
#define HOP_STAGE (128 * HRS)
#define HSTG (2 * HOP_STAGE)
#define GEMM_SMEM_BYTES (3 * HSTG * 2)   // 61,440 B

template <bool RELU, bool BIAS, int OUTMODE>
__global__ void __launch_bounds__(256, 2) gemm_f16(
    const __half* __restrict__ A, const __half* __restrict__ BT,
    const float* __restrict__ bias, void* __restrict__ Cv,
    int M, int N, int K)
{
    extern __shared__ __half smh[];

    const int tid  = threadIdx.x;
    const int bm   = blockIdx.y * 128;
    const int bn   = blockIdx.x * 128;
    const int wid  = tid >> 5;
    const int lane = tid & 31;
    const int g    = lane >> 2;
    const int t    = lane & 3;
    const int wm   = (wid & 3) * 32;
    const int wn   = (wid >> 2) * 64;

    const uint32_t sbase = (uint32_t)__cvta_generic_to_shared(smh);
    const int nk = K / GBK;

    auto load_stage = [&](int slot, int k0) {
#pragma unroll
        for (int i = 0; i < 2; i++) {
            int id = tid + i * 256;
            int r  = id >> 2;
            int cb = (id & 3) << 4;
            uint32_t dstA = sbase + (uint32_t)(slot * HSTG * 2 + r * (HRS * 2) + cb);
            uint32_t dstB = dstA + HOP_STAGE * 2;
            const __half* srcA = A  + (size_t)(bm + r) * K + k0 + (cb >> 1);
            const __half* srcB = BT + (size_t)(bn + r) * K + k0 + (cb >> 1);
            asm volatile("cp.async.cg.shared.global [%0], [%1], 16;\n"
                         :: "r"(dstA), "l"(srcA));
            asm volatile("cp.async.cg.shared.global [%0], [%1], 16;\n"
                         :: "r"(dstB), "l"(srcB));
        }
    };

    float acc[2][8][4];
#pragma unroll
    for (int mi = 0; mi < 2; mi++)
#pragma unroll
        for (int ni = 0; ni < 8; ni++)
#pragma unroll
            for (int e = 0; e < 4; e++) acc[mi][ni][e] = 0.f;

    load_stage(0, 0);
    asm volatile("cp.async.commit_group;\n");
    load_stage(1, GBK);
    asm volatile("cp.async.commit_group;\n");

    for (int kt = 0; kt < nk; kt++) {
        asm volatile("cp.async.wait_group 1;\n");
        __syncthreads();
        if (kt + 2 < nk) load_stage((kt + 2) % 3, (kt + 2) * GBK);
        asm volatile("cp.async.commit_group;\n");

        const __half* Asc = smh + (kt % 3) * HSTG;
        const __half* Bsc = Asc + HOP_STAGE;

#pragma unroll
        for (int kk = 0; kk < GBK; kk += 16) {
            uint32_t af[2][4], bf[8][2];
#pragma unroll
            for (int mi = 0; mi < 2; mi++) {
                const int r = wm + mi * 16 + g;
                af[mi][0] = *(const uint32_t*)&Asc[r * HRS + kk + 2 * t];
                af[mi][1] = *(const uint32_t*)&Asc[(r + 8) * HRS + kk + 2 * t];
                af[mi][2] = *(const uint32_t*)&Asc[r * HRS + kk + 2 * t + 8];
                af[mi][3] = *(const uint32_t*)&Asc[(r + 8) * HRS + kk + 2 * t + 8];
            }
#pragma unroll
            for (int ni = 0; ni < 8; ni++) {
                const int c = wn + ni * 8 + g;
                bf[ni][0] = *(const uint32_t*)&Bsc[c * HRS + kk + 2 * t];
                bf[ni][1] = *(const uint32_t*)&Bsc[c * HRS + kk + 2 * t + 8];
            }
#pragma unroll
            for (int mi = 0; mi < 2; mi++)
#pragma unroll
                for (int ni = 0; ni < 8; ni++) {
                    float* d = acc[mi][ni];
                    asm volatile(
                        "mma.sync.aligned.m16n8k16.row.col.f32.f16.f16.f32 "
                        "{%0,%1,%2,%3}, {%4,%5,%6,%7}, {%8,%9}, {%0,%1,%2,%3};\n"
                        : "+f"(d[0]), "+f"(d[1]), "+f"(d[2]), "+f"(d[3])
                        : "r"(af[mi][0]), "r"(af[mi][1]), "r"(af[mi][2]), "r"(af[mi][3]),
                          "r"(bf[ni][0]), "r"(bf[ni][1]));
                }
        }
    }

#pragma unroll
    for (int mi = 0; mi < 2; mi++) {
#pragma unroll
        for (int ni = 0; ni < 8; ni++) {
            const int row = bm + wm + mi * 16 + g;
            const int col = bn + wn + ni * 8 + (t << 1);
            float v0 = acc[mi][ni][0], v1 = acc[mi][ni][1];
            float v2 = acc[mi][ni][2], v3 = acc[mi][ni][3];
            if (BIAS) {
                const float b0 = bias[col], b1 = bias[col + 1];
                v0 += b0; v1 += b1; v2 += b0; v3 += b1;
            }
            if (RELU) {
                v0 = fmaxf(v0, 0.f); v1 = fmaxf(v1, 0.f);
                v2 = fmaxf(v2, 0.f); v3 = fmaxf(v3, 0.f);
            }
            if (OUTMODE == 2) {
                __half* Ch = (__half*)Cv;
                *(__half2*)&Ch[(size_t)row * N + col]       = __floats2half2_rn(v0, v1);
                *(__half2*)&Ch[(size_t)(row + 8) * N + col] = __floats2half2_rn(v2, v3);
            } else {
                float* Cf = (float*)Cv;
                *(float2*)&Cf[(size_t)row * N + col]       = make_float2(v0, v1);
                *(float2*)&Cf[(size_t)(row + 8) * N + col] = make_float2(v2, v3);
            }
        }
    }
}

// ---------------------------------------------------------------------------
// FP16 flash attention (m16n8k16). Same decomposition as the passing tf32
// version: 8 warps, warp w owns rows [w*16,w*16+16) x full 64-key tile;
// K/V double-buffered cp.async; mask+pad staged via smem.
// Q/K/P tiles: [row][dim] half, stride 72 halves (144 B) — A/B frags are
// contiguous half2, conflict-free (word = 4g+t). V B-frag packs 2 keys per
// register via LDS.U16 pairs (16 distinct words, no conflicts).
// ---------------------------------------------------------------------------
#define KTT 64
#define NTT (LL / KTT)
#define HS  72                             // half stride per row
#define QSB (HS * 2)                       // 144 B
#define QB_OFF  0
#define KB_OFF  (128 * QSB)                // 18432
#define KSTG_B  (64 * QSB)                 // 9216
#define VB_OFF  (KB_OFF + 2 * KSTG_B)      // 36864
#define PB_OFF  (VB_OFF + 2 * KSTG_B)      // 55296
#define MB_OFF  (PB_OFF + 128 * QSB)       // 73728  (mask fp32, stride 68 floats)
#define MSF 68
#define PDB_OFF (MB_OFF + 128 * MSF * 4)   // 108544
#define ATT_SMEM_BYTES (PDB_OFF + 256)     // 108800

__global__ void __launch_bounds__(256) attn_f16_kernel(
    const __half* __restrict__ Qb, const __half* __restrict__ Kb,
    const __half* __restrict__ Vb, const float* __restrict__ mask,
    const float* __restrict__ padf, __half* __restrict__ ctx)
{
    extern __shared__ char smc[];
    const uint32_t sbase = (uint32_t)__cvta_generic_to_shared(smc);

    const int b   = blockIdx.y >> 4;
    const int h   = blockIdx.y & 15;
    const int q0  = blockIdx.x * 128;
    const int tid = threadIdx.x;
    const int wid = tid >> 5;
    const int lane = tid & 31;
    const int g   = lane >> 2;
    const int t   = lane & 3;
    const int wm  = wid * 16;

    // ---- prologue: Q tile [128x64] + K/V tile 0 (one group) ----
#pragma unroll
    for (int i = 0; i < 4; i++) {
        int id = tid + i * 256;              // 0..1023
        int r = id >> 3, ch = id & 7;        // 8 x 16B chunks per row
        uint32_t dst = sbase + QB_OFF + r * QSB + ch * 16;
        const __half* src = Qb + (size_t)(b * LL + q0 + r) * DD + h * HDIM + ch * 8;
        asm volatile("cp.async.cg.shared.global [%0], [%1], 16;\n" :: "r"(dst), "l"(src));
    }
#pragma unroll
    for (int i = 0; i < 2; i++) {
        int id = tid + i * 256;              // 0..511
        int r = id >> 3, ch = id & 7;
        size_t go = (size_t)(b * LL + r) * DD + h * HDIM + ch * 8;
        uint32_t dk = sbase + KB_OFF + r * QSB + ch * 16;
        uint32_t dv = sbase + VB_OFF + r * QSB + ch * 16;
        asm volatile("cp.async.cg.shared.global [%0], [%1], 16;\n" :: "r"(dk), "l"(Kb + go));
        asm volatile("cp.async.cg.shared.global [%0], [%1], 16;\n" :: "r"(dv), "l"(Vb + go));
    }
    asm volatile("cp.async.commit_group;\n");

    float o[8][4];
    float mrow[2] = {-1e30f, -1e30f}, lrow[2] = {0.f, 0.f};
#pragma unroll
    for (int ni = 0; ni < 8; ni++)
#pragma unroll
        for (int e = 0; e < 4; e++) o[ni][e] = 0.f;

    const float* Mf  = (const float*)(smc + MB_OFF);
    const float* Pdf = (const float*)(smc + PDB_OFF);
    __half* Ph = (__half*)(smc + PB_OFF);
    const __half* Qh = (const __half*)(smc + QB_OFF);

    for (int kt = 0; kt < NTT; kt++) {
        const int k0 = kt * KTT;
        const int cur = kt & 1;
        const int nxt = cur ^ 1;

        asm volatile("cp.async.wait_group 0;\n");   // K/V(kt) + prior mask done
        __syncthreads();

        // stage mask+pad tile kt (own group) — consumed after S-MMA
#pragma unroll
        for (int i = 0; i < 8; i++) {
            int id = tid + i * 256;                  // 0..2047
            int r = id >> 4, c = (id & 15) << 2;     // 16 x 16B chunks per row
            uint32_t dm = sbase + MB_OFF + r * (MSF * 4) + c * 4;
            const float* srcm = mask + (size_t)(q0 + r) * LL + k0 + c;
            asm volatile("cp.async.cg.shared.global [%0], [%1], 16;\n" :: "r"(dm), "l"(srcm));
        }
        if (tid < 16) {
            uint32_t dp = sbase + PDB_OFF + tid * 16;
            const float* srcp = padf + b * LL + k0 + tid * 4;
            asm volatile("cp.async.cg.shared.global [%0], [%1], 16;\n" :: "r"(dp), "l"(srcp));
        }
        asm volatile("cp.async.commit_group;\n");

        // prefetch K/V(kt+1) (own group)
        if (kt + 1 < NTT) {
#pragma unroll
            for (int i = 0; i < 2; i++) {
                int id = tid + i * 256;
                int r = id >> 3, ch = id & 7;
                size_t go = (size_t)(b * LL + k0 + KTT + r) * DD + h * HDIM + ch * 8;
                uint32_t dk = sbase + KB_OFF + nxt * KSTG_B + r * QSB + ch * 16;
                uint32_t dv = sbase + VB_OFF + nxt * KSTG_B + r * QSB + ch * 16;
                asm volatile("cp.async.cg.shared.global [%0], [%1], 16;\n" :: "r"(dk), "l"(Kb + go));
                asm volatile("cp.async.cg.shared.global [%0], [%1], 16;\n" :: "r"(dv), "l"(Vb + go));
            }
        }
        asm volatile("cp.async.commit_group;\n");

        const __half* Kh = (const __half*)(smc + KB_OFF + cur * KSTG_B);
        const __half* Vh = (const __half*)(smc + VB_OFF + cur * KSTG_B);

        // ---- S[16 x 64] = Q @ K^T  (m16n8k16) ----
        float s[8][4];
#pragma unroll
        for (int ni = 0; ni < 8; ni++)
#pragma unroll
            for (int e = 0; e < 4; e++) s[ni][e] = 0.f;

#pragma unroll
        for (int kk = 0; kk < HDIM; kk += 16) {
            uint32_t af[4], bf[8][2];
            af[0] = *(const uint32_t*)&Qh[(wm + g) * HS + kk + 2 * t];
            af[1] = *(const uint32_t*)&Qh[(wm + g + 8) * HS + kk + 2 * t];
            af[2] = *(const uint32_t*)&Qh[(wm + g) * HS + kk + 2 * t + 8];
            af[3] = *(const uint32_t*)&Qh[(wm + g + 8) * HS + kk + 2 * t + 8];
#pragma unroll
            for (int ni = 0; ni < 8; ni++) {
                const int key = ni * 8 + g;
                bf[ni][0] = *(const uint32_t*)&Kh[key * HS + kk + 2 * t];
                bf[ni][1] = *(const uint32_t*)&Kh[key * HS + kk + 2 * t + 8];
            }
#pragma unroll
            for (int ni = 0; ni < 8; ni++) {
                float* d = s[ni];
                asm volatile(
                    "mma.sync.aligned.m16n8k16.row.col.f32.f16.f16.f32 "
                    "{%0,%1,%2,%3}, {%4,%5,%6,%7}, {%8,%9}, {%0,%1,%2,%3};\n"
                    : "+f"(d[0]), "+f"(d[1]), "+f"(d[2]), "+f"(d[3])
                    : "r"(af[0]), "r"(af[1]), "r"(af[2]), "r"(af[3]),
                      "r"(bf[ni][0]), "r"(bf[ni][1]));
            }
        }

        asm volatile("cp.async.wait_group 1;\n");   // mask ready; next K/V may pend
        __syncthreads();

        // ---- online softmax over 64 keys (warp-local rows) ----
#pragma unroll
        for (int hf = 0; hf < 2; hf++) {
            const int r = wm + g + hf * 8;
            float rm = -1e30f;
#pragma unroll
            for (int ni = 0; ni < 8; ni++) {
                const int kcl = ni * 8 + (t << 1);
                const float2 mk = *(const float2*)&Mf[r * MSF + kcl];
                float v0 = s[ni][hf * 2 + 0] * 0.125f + mk.x + Pdf[kcl];
                float v1 = s[ni][hf * 2 + 1] * 0.125f + mk.y + Pdf[kcl + 1];
                s[ni][hf * 2 + 0] = v0;
                s[ni][hf * 2 + 1] = v1;
                rm = fmaxf(rm, fmaxf(v0, v1));
            }
            rm = fmaxf(rm, __shfl_xor_sync(0xffffffffu, rm, 1));
            rm = fmaxf(rm, __shfl_xor_sync(0xffffffffu, rm, 2));
            const float mnew = fmaxf(mrow[hf], rm);
            const float corr = __expf(mrow[hf] - mnew);
            mrow[hf] = mnew;
            float rs = 0.f;
#pragma unroll
            for (int ni = 0; ni < 8; ni++) {
                float p0 = __expf(s[ni][hf * 2 + 0] - mnew);
                float p1 = __expf(s[ni][hf * 2 + 1] - mnew);
                rs += p0 + p1;
                *(__half2*)&Ph[r * HS + ni * 8 + (t << 1)] = __floats2half2_rn(p0, p1);
            }
            rs += __shfl_xor_sync(0xffffffffu, rs, 1);
            rs += __shfl_xor_sync(0xffffffffu, rs, 2);
            lrow[hf] = lrow[hf] * corr + rs;
#pragma unroll
            for (int ni = 0; ni < 8; ni++) {
                o[ni][hf * 2 + 0] *= corr;
                o[ni][hf * 2 + 1] *= corr;
            }
        }
        __syncwarp();   // P rows are warp-private

        // ---- O[16 x 64] += P @ V  (m16n8k16; V packed 2 keys/reg) ----
#pragma unroll
        for (int kk = 0; kk < KTT; kk += 16) {
            uint32_t ap[4], bv[8][2];
            ap[0] = *(const uint32_t*)&Ph[(wm + g) * HS + kk + 2 * t];
            ap[1] = *(const uint32_t*)&Ph[(wm + g + 8) * HS + kk + 2 * t];
            ap[2] = *(const uint32_t*)&Ph[(wm + g) * HS + kk + 2 * t + 8];
            ap[3] = *(const uint32_t*)&Ph[(wm + g + 8) * HS + kk + 2 * t + 8];
#pragma unroll
            for (int ni = 0; ni < 8; ni++) {
                const int c = ni * 8 + g;
                __half2 b0h, b1h;
                b0h.x = Vh[(kk + 2 * t) * HS + c];
                b0h.y = Vh[(kk + 2 * t + 1) * HS + c];
                b1h.x = Vh[(kk + 2 * t + 8) * HS + c];
                b1h.y = Vh[(kk + 2 * t + 9) * HS + c];
                bv[ni][0] = *(const uint32_t*)&b0h;
                bv[ni][1] = *(const uint32_t*)&b1h;
            }
#pragma unroll
            for (int ni = 0; ni < 8; ni++) {
                float* d = o[ni];
                asm volatile(
                    "mma.sync.aligned.m16n8k16.row.col.f32.f16.f16.f32 "
                    "{%0,%1,%2,%3}, {%4,%5,%6,%7}, {%8,%9}, {%0,%1,%2,%3};\n"
                    : "+f"(d[0]), "+f"(d[1]), "+f"(d[2]), "+f"(d[3])
                    : "r"(ap[0]), "r"(ap[1]), "r"(ap[2]), "r"(ap[3]),
                      "r"(bv[ni][0]), "r"(bv[ni][1]));
            }
        }
    }

    // ---- epilogue: normalize, store ctx as fp16 (feeds Wo GEMM) ----
    const float inv0 = 1.f / lrow[0];
    const float inv1 = 1.f / lrow[1];
#pragma unroll
    for (int ni = 0; ni < 8; ni++) {
        const int col = h * HDIM + ni * 8 + (t << 1);
        *(__half2*)&ctx[(size_t)(b * LL + q0 + wm + g) * DD + col] =
            __floats2half2_rn(o[ni][0] * inv0, o[ni][1] * inv0);
        *(__half2*)&ctx[(size_t)(b * LL + q0 + wm + g + 8) * DD + col] =
            __floats2half2_rn(o[ni][2] * inv1, o[ni][3] * inv1);
    }
}

// ---------------------------------------------------------------------------
// LayerNorm(x + r) * g + b -> dual output: fp32 (residual) + fp16 (GEMM A)
// ---------------------------------------------------------------------------
__global__ void __launch_bounds__(256) ln_residual_kernel(
    const float* __restrict__ x, const float* __restrict__ r,
    const float* __restrict__ g, const float* __restrict__ be,
    float* __restrict__ outf, __half* __restrict__ outh)
{
    __shared__ float red[8];
    const int row = blockIdx.x;
    const int t = threadIdx.x;

    const float4 a = ((const float4*)(x + (size_t)row * DD))[t];
    const float4 c = ((const float4*)(r + (size_t)row * DD))[t];
    float4 v = make_float4(a.x + c.x, a.y + c.y, a.z + c.z, a.w + c.w);

    float s = v.x + v.y + v.z + v.w;
#pragma unroll
    for (int o = 16; o >= 1; o >>= 1) s += __shfl_xor_sync(0xffffffffu, s, o);
    if ((t & 31) == 0) red[t >> 5] = s;
    __syncthreads();
    float tot = red[0] + red[1] + red[2] + red[3] + red[4] + red[5] + red[6] + red[7];
    const float mean = tot * (1.0f / DD);

    const float dx0 = v.x - mean, dx1 = v.y - mean, dx2 = v.z - mean, dx3 = v.w - mean;
    float sq = dx0 * dx0 + dx1 * dx1 + dx2 * dx2 + dx3 * dx3;
#pragma unroll
    for (int o = 16; o >= 1; o >>= 1) sq += __shfl_xor_sync(0xffffffffu, sq, o);
    __syncthreads();
    if ((t & 31) == 0) red[t >> 5] = sq;
    __syncthreads();
    float var = (red[0] + red[1] + red[2] + red[3] + red[4] + red[5] + red[6] + red[7]) * (1.0f / DD);
    const float rstd = rsqrtf(var + 1e-5f);

    const float4 gg = ((const float4*)g)[t];
    const float4 bb = ((const float4*)be)[t];
    float4 ov;
    ov.x = dx0 * rstd * gg.x + bb.x;
    ov.y = dx1 * rstd * gg.y + bb.y;
    ov.z = dx2 * rstd * gg.z + bb.z;
    ov.w = dx3 * rstd * gg.w + bb.w;
    ((float4*)(outf + (size_t)row * DD))[t] = ov;
    __half2* oh = (__half2*)(outh + (size_t)row * DD) + 2 * t;
    oh[0] = __floats2half2_rn(ov.x, ov.y);
    oh[1] = __floats2half2_rn(ov.z, ov.w);
}

// ---------------------------------------------------------------------------
// Launch
// ---------------------------------------------------------------------------
extern "C" void kernel_launch(void* const* d_in, const int* in_sizes, int n_in,
                              void* d_out, int out_size)
{
    const float* T    = (const float*)d_in[0];
    const float* A    = (const float*)d_in[1];
    const float* mask = (const float*)d_in[2];
    const int*   pad  = (const int*)  d_in[3];
    const float* Wq   = (const float*)d_in[4];
    const float* bq   = (const float*)d_in[5];
    const float* Wk   = (const float*)d_in[6];
    const float* bk   = (const float*)d_in[7];
    const float* Wv   = (const float*)d_in[8];
    const float* bv   = (const float*)d_in[9];
    const float* Wo   = (const float*)d_in[10];
    const float* fW1  = (const float*)d_in[11];
    const float* fb1  = (const float*)d_in[12];
    const float* fW2  = (const float*)d_in[13];
    const float* fb2  = (const float*)d_in[14];
    const float* lng  = (const float*)d_in[15];
    const float* lnb  = (const float*)d_in[16];
    float* out = (float*)d_out;

    float *proj, *t1f, *a1f, *t2f, *a2f, *padf;
    __half *q, *k, *v, *ctx, *t1h, *a1h, *t2h, *a2h, *ffh, *tr, *ar;
    __half *wq, *wk, *wv, *wo, *fw1, *fw2;
    cudaGetSymbolAddress((void**)&q,    g_q);
    cudaGetSymbolAddress((void**)&k,    g_k);
    cudaGetSymbolAddress((void**)&v,    g_v);
    cudaGetSymbolAddress((void**)&ctx,  g_ctx);
    cudaGetSymbolAddress((void**)&proj, g_proj);
    cudaGetSymbolAddress((void**)&t1f,  g_t1f);
    cudaGetSymbolAddress((void**)&a1f,  g_a1f);
    cudaGetSymbolAddress((void**)&t2f,  g_t2f);
    cudaGetSymbolAddress((void**)&a2f,  g_a2f);
    cudaGetSymbolAddress((void**)&t1h,  g_t1h);
    cudaGetSymbolAddress((void**)&a1h,  g_a1h);
    cudaGetSymbolAddress((void**)&t2h,  g_t2h);
    cudaGetSymbolAddress((void**)&a2h,  g_a2h);
    cudaGetSymbolAddress((void**)&ffh,  g_ffh);
    cudaGetSymbolAddress((void**)&tr,   g_tr);
    cudaGetSymbolAddress((void**)&ar,   g_ar);
    cudaGetSymbolAddress((void**)&wq,   g_wq);
    cudaGetSymbolAddress((void**)&wk,   g_wk);
    cudaGetSymbolAddress((void**)&wv,   g_wv);
    cudaGetSymbolAddress((void**)&wo,   g_wo);
    cudaGetSymbolAddress((void**)&fw1,  g_fw1);
    cudaGetSymbolAddress((void**)&fw2,  g_fw2);
    cudaGetSymbolAddress((void**)&padf, g_padf);

    cudaFuncSetAttribute(attn_f16_kernel,
                         cudaFuncAttributeMaxDynamicSharedMemorySize, ATT_SMEM_BYTES);
    cudaFuncSetAttribute(gemm_f16<false, true,  2>,
                         cudaFuncAttributeMaxDynamicSharedMemorySize, GEMM_SMEM_BYTES);
    cudaFuncSetAttribute(gemm_f16<false, false, 0>,
                         cudaFuncAttributeMaxDynamicSharedMemorySize, GEMM_SMEM_BYTES);
    cudaFuncSetAttribute(gemm_f16<true,  true,  2>,
                         cudaFuncAttributeMaxDynamicSharedMemorySize, GEMM_SMEM_BYTES);
    cudaFuncSetAttribute(gemm_f16<false, true,  0>,
                         cudaFuncAttributeMaxDynamicSharedMemorySize, GEMM_SMEM_BYTES);

    // ---- pre-pass: inputs -> fp16; weights -> transposed fp16 ----
    const int RB = 256;
    auto th = [&](const float* src, __half* dst, size_t nfloats) {
        int n4 = (int)(nfloats / 4);
        int grid = (n4 + RB * 4 - 1) / (RB * 4);
        tohalf_kernel<<<grid, RB>>>((const float4*)src, (__half2*)dst, n4);
    };
    th(T, tr, (size_t)MM * DD);
    th(A, ar, (size_t)MM * DD);
    dim3 tb(32, 8);
    auto tp = [&](const float* src, __half* dst, int K, int N) {
        transpose_half_kernel<<<dim3(N / 32, K / 32), tb>>>(src, dst, K, N);
    };
    for (int i = 0; i < 4; i++) {
        tp(Wq + (size_t)i * DD * DD, wq + (size_t)i * DD * DD, DD, DD);
        tp(Wk + (size_t)i * DD * DD, wk + (size_t)i * DD * DD, DD, DD);
        tp(Wv + (size_t)i * DD * DD, wv + (size_t)i * DD * DD, DD, DD);
        tp(Wo + (size_t)i * DD * DD, wo + (size_t)i * DD * DD, DD, DD);
    }
    for (int i = 0; i < 2; i++) {
        tp(fW1 + (size_t)i * DD * FFD, fw1 + (size_t)i * FFD * DD, DD, FFD);
        tp(fW2 + (size_t)i * FFD * DD, fw2 + (size_t)i * DD * FFD, FFD, DD);
    }
    pad_to_float_kernel<<<(BB * LL + 255) / 256, 256>>>(pad, padf, BB * LL);

    dim3 thr(256);
    dim3 gP (DD  / 128, MM / 128);
    dim3 gF1(FFD / 128, MM / 128);
    dim3 gA (LL / 128, BB * HH);

    auto run_mha = [&](int i, const __half* xq, const __half* xkv,
                       const float* resid, float* destf, __half* desth) {
        gemm_f16<false, true,  2><<<gP, thr, GEMM_SMEM_BYTES>>>(xq,  wq + (size_t)i * DD * DD, bq + i * DD, q, MM, DD, DD);
        gemm_f16<false, true,  2><<<gP, thr, GEMM_SMEM_BYTES>>>(xkv, wk + (size_t)i * DD * DD, bk + i * DD, k, MM, DD, DD);
        gemm_f16<false, true,  2><<<gP, thr, GEMM_SMEM_BYTES>>>(xkv, wv + (size_t)i * DD * DD, bv + i * DD, v, MM, DD, DD);
        attn_f16_kernel<<<gA, thr, ATT_SMEM_BYTES>>>(q, k, v, mask, padf, ctx);
        gemm_f16<false, false, 0><<<gP, thr, GEMM_SMEM_BYTES>>>(ctx, wo + (size_t)i * DD * DD, nullptr, proj, MM, DD, DD);
        ln_residual_kernel<<<MM, thr>>>(resid, proj, lng + i * DD, lnb + i * DD, destf, desth);
    };

    run_mha(0, tr,  tr,  T,   t1f, t1h);
    run_mha(1, ar,  ar,  A,   a1f, a1h);
    run_mha(2, t1h, a1h, t1f, t2f, t2h);
    run_mha(3, a1h, t2h, a1f, a2f, a2h);

    gemm_f16<true,  true, 2><<<gF1, thr, GEMM_SMEM_BYTES>>>(t2h, fw1, fb1, ffh, MM, FFD, DD);
    gemm_f16<false, true, 0><<<gP,  thr, GEMM_SMEM_BYTES>>>(ffh, fw2, fb2, out, MM, DD, FFD);
    gemm_f16<true,  true, 2><<<gF1, thr, GEMM_SMEM_BYTES>>>(a2h, fw1 + (size_t)FFD * DD, fb1 + FFD, ffh, MM, FFD, DD);
    gemm_f16<false, true, 0><<<gP,  thr, GEMM_SMEM_BYTES>>>(ffh, fw2 + (size_t)DD * FFD, fb2 + DD,
                                                            out + (size_t)MM * DD, MM, DD, FFD);
}